// round 13
// baseline (speedup 1.0000x reference)
#include <cuda_runtime.h>
#include <cuda_fp16.h>
#include <math.h>
#include <stdint.h>

#define BB 4
#define SS 2048
#define DD 2048
#define DI 1024
#define MM (BB*SS)      // 8192
#define KK DD
#define NN DD
#define D4 (DD/4)
#define S4 (SS/4)       // 512

// GEMM tiling: CTA 128x128, 8 warps (4M x 2N), warp tile 32x64, BKK=64, 3 stages
#define BM 128
#define BN 128
#define BKK 64
#define ASZ (BM*BKK)    // 8192 halves
#define BSZ (BKK*BN)    // 8192 halves
#define NSTAGE 3
#define STG_H (ASZ + BSZ)
#define SMEM_BYTES (NSTAGE*STG_H*2)    // 98304

// ---------------- scratch ---------------------------------------------------
__device__ __half g_x2[(size_t)MM*KK];
__device__ __half g_y [(size_t)MM*KK];
__device__ __half g_pw[(size_t)KK*NN];
__device__ __half g_ow[(size_t)KK*NN];
__device__ float g_fs2[(size_t)MM*3*32];
__device__ float g_fs [(size_t)MM*3];
__device__ float g_w [BB*3];

__device__ __forceinline__ float geluf(float v) {
    return 0.5f * v * (1.0f + erff(v * 0.70710678118654752f));
}
__device__ __forceinline__ uint32_t smem_u32(const void* p) {
    return (uint32_t)__cvta_generic_to_shared(p);
}

#define CP16(s, g) asm volatile("cp.async.cg.shared.global [%0], [%1], 16;\n" :: "r"(s), "l"(g))
#define CP_COMMIT() asm volatile("cp.async.commit_group;\n")
#define LDSM4(R0,R1,R2,R3,addr) \
    asm volatile("ldmatrix.sync.aligned.m8n8.x4.shared.b16 {%0,%1,%2,%3},[%4];" \
                 : "=r"(R0),"=r"(R1),"=r"(R2),"=r"(R3) : "r"(addr))
#define LDSM4T(R0,R1,R2,R3,addr) \
    asm volatile("ldmatrix.sync.aligned.m8n8.x4.trans.shared.b16 {%0,%1,%2,%3},[%4];" \
                 : "=r"(R0),"=r"(R1),"=r"(R2),"=r"(R3) : "r"(addr))
#define MMAH16816(D0,D1,D2,D3,A0,A1,A2,A3,B0,B1) \
    asm volatile("mma.sync.aligned.m16n8k16.row.col.f32.f16.f16.f32 " \
                 "{%0,%1,%2,%3},{%4,%5,%6,%7},{%8,%9},{%0,%1,%2,%3};" \
                 : "+f"(D0),"+f"(D1),"+f"(D2),"+f"(D3) \
                 : "r"(A0),"r"(A1),"r"(A2),"r"(A3),"r"(B0),"r"(B1))

// ------- fused prologue: convert proj_w, convert out_w, shortconv ----------
__global__ void prep_kernel(const float* __restrict__ x,
                            const float* __restrict__ sw,
                            const float* __restrict__ sb,
                            const float* __restrict__ pw,
                            const float* __restrict__ ow)
{
    const int blk = blockIdx.x;
    if (blk < 8192) {
        const float* src = (blk < 4096) ? pw : ow;
        __half* dst = (blk < 4096) ? g_pw : g_ow;
        int i = (blk & 4095) * 256 + threadIdx.x;
        size_t base = (size_t)i * 4;
        float4 v = *(const float4*)(src + base);
        *(__half2*)(dst + base)     = __floats2half2_rn(v.x, v.y);
        *(__half2*)(dst + base + 2) = __floats2half2_rn(v.z, v.w);
        return;
    }
    int idx = (blk - 8192) * 256 + threadIdx.x;
    int d4 = idx % D4;
    int g  = idx / D4;
    int s0 = (g & (S4 - 1)) * 4;
    int b  = g >> 9;
    int d  = d4 * 4;
    size_t rowbase = ((size_t)(b*SS + s0))*DD + d;

    float4 r[6];
    #pragma unroll
    for (int i = 0; i < 6; i++) {
        int s = s0 + i - 2;
        r[i] = (s >= 0) ? *(const float4*)(x + rowbase + (ptrdiff_t)(i-2)*DD)
                        : make_float4(0.f, 0.f, 0.f, 0.f);
    }
    float w0[4], w1[4], w2[4], bb[4];
    #pragma unroll
    for (int q = 0; q < 4; q++) {
        w0[q] = sw[(d+q)*3+0]; w1[q] = sw[(d+q)*3+1]; w2[q] = sw[(d+q)*3+2];
        bb[q] = sb[d+q];
    }
    #pragma unroll
    for (int i = 0; i < 4; i++) {
        const float cv[4] = {r[i+2].x, r[i+2].y, r[i+2].z, r[i+2].w};
        const float pv[4] = {r[i+1].x, r[i+1].y, r[i+1].z, r[i+1].w};
        const float qv[4] = {r[i].x,   r[i].y,   r[i].z,   r[i].w};
        float o[4];
        #pragma unroll
        for (int q = 0; q < 4; q++)
            o[q] = cv[q] + bb[q] + qv[q]*w0[q] + pv[q]*w1[q] + cv[q]*w2[q];
        size_t ob = rowbase + (size_t)i*DD;
        *(__half2*)(g_x2 + ob)     = __floats2half2_rn(o[0], o[1]);
        *(__half2*)(g_x2 + ob + 2) = __floats2half2_rn(o[2], o[3]);
    }
}

// ------- fp16 tensor-core GEMM: 128x128 tile, 8 warps (4Mx2N), 32x64 wtile --
template<int REDUCE>
__global__ void __launch_bounds__(256, 2)
gemm_h(const __half* __restrict__ A, const __half* __restrict__ B,
       const float* __restrict__ bias, float* __restrict__ C,
       const float* __restrict__ fw)
{
    extern __shared__ __half sm[];

    const int tid  = threadIdx.x;
    const int bm   = blockIdx.y, bn = blockIdx.x;
    const int warp = tid >> 5, lane = tid & 31;
    const int mwarp = (warp & 3) * 32;     // 4 warps in M
    const int nwarp = (warp >> 2) * 64;    // 2 warps in N

    const uint32_t base0 = smem_u32(sm);

    auto issue = [&](int stg, int t) {
        uint32_t aS = base0 + (uint32_t)stg*STG_H*2;
        uint32_t bS = aS + ASZ*2;
        const __half* gAt = A + (size_t)(bm*BM)*KK + (size_t)t*BKK;
        const __half* gBt = B + (size_t)((size_t)t*BKK)*NN + bn*BN;
        // A: 1024 16B chunks, 4 per thread
        #pragma unroll
        for (int j = 0; j < 4; j++) {
            int idx = tid + 256*j;
            int row = idx >> 3, ch = idx & 7;
            uint32_t so = (uint32_t)row*128u + (uint32_t)(((ch ^ (row & 7)) << 4));
            CP16(aS + so, gAt + (size_t)row*KK + ch*8);
        }
        // B: 1024 chunks, 4 per thread (64 rows x 16 chunks)
        #pragma unroll
        for (int j = 0; j < 4; j++) {
            int idx = tid + 256*j;
            int row = idx >> 4, ch = idx & 15;
            uint32_t so = (uint32_t)row*256u + (uint32_t)(((ch ^ (row & 7)) << 4));
            CP16(bS + so, gBt + (size_t)row*NN + ch*8);
        }
        CP_COMMIT();
    };

    float acc[2][8][4];
    #pragma unroll
    for (int i = 0; i < 2; i++)
        #pragma unroll
        for (int j = 0; j < 8; j++)
            #pragma unroll
            for (int q = 0; q < 4; q++) acc[i][j][q] = 0.f;

    const int lr  = lane & 15;
    const int hc  = lane >> 4;
    const int swz = lr & 7;
    int rowA[2];
    rowA[0] = mwarp + lr;
    rowA[1] = mwarp + 16 + lr;
    const int ncbase = (warp >> 2) * 8;    // base 16B chunk in 256B B row

    const int NT = KK / BKK;               // 32
    issue(0, 0);
    issue(1, 1);

    for (int t = 0; t < NT; ++t) {
        const int stg = t % NSTAGE;
        asm volatile("cp.async.wait_group %0;\n" :: "n"(NSTAGE - 2));
        __syncthreads();
        if (t + 2 < NT) issue((t + 2) % NSTAGE, t + 2);

        const uint32_t aS = base0 + (uint32_t)stg*STG_H*2;
        const uint32_t bS = aS + ASZ*2;

        #pragma unroll
        for (int ks = 0; ks < 4; ks++) {
            const int krow = ks*16 + lr;
            uint32_t af[2][4];
            {
                int chunk = (2*ks + hc) ^ swz;
                LDSM4(af[0][0], af[0][1], af[0][2], af[0][3],
                      aS + (uint32_t)rowA[0]*128 + chunk*16);
                LDSM4(af[1][0], af[1][1], af[1][2], af[1][3],
                      aS + (uint32_t)rowA[1]*128 + chunk*16);
            }
            #pragma unroll
            for (int p = 0; p < 4; p++) {
                int chunk = (ncbase + 2*p + hc) ^ swz;
                uint32_t b0, b1, b2, b3;
                LDSM4T(b0, b1, b2, b3, bS + (uint32_t)krow*256 + chunk*16);
                #pragma unroll
                for (int mt = 0; mt < 2; mt++) {
                    MMAH16816(acc[mt][2*p+0][0],acc[mt][2*p+0][1],acc[mt][2*p+0][2],acc[mt][2*p+0][3],
                              af[mt][0],af[mt][1],af[mt][2],af[mt][3], b0,b1);
                    MMAH16816(acc[mt][2*p+1][0],acc[mt][2*p+1][1],acc[mt][2*p+1][2],acc[mt][2*p+1][3],
                              af[mt][0],af[mt][1],af[mt][2],af[mt][3], b2,b3);
                }
            }
        }
    }

    // ---- epilogue ----
    const int g  = lane >> 2;
    const int tg = lane & 3;

    if (REDUCE) {
        float part[2][2][3];
        #pragma unroll
        for (int mt = 0; mt < 2; mt++)
            #pragma unroll
            for (int r = 0; r < 2; r++)
                #pragma unroll
                for (int k = 0; k < 3; k++) part[mt][r][k] = 0.f;

        #pragma unroll
        for (int nn = 0; nn < 8; nn++) {
            const int col = bn*BN + nwarp + nn*8 + tg*2;
            const float b0 = bias[col], b1 = bias[col+1];
            const int i0 = col & (DI-1);
            float fw0[3], fw1[3];
            #pragma unroll
            for (int k = 0; k < 3; k++) { fw0[k] = fw[i0*3+k]; fw1[k] = fw[(i0+1)*3+k]; }
            #pragma unroll
            for (int mt = 0; mt < 2; mt++) {
                float v0 = geluf(acc[mt][nn][0] + b0);
                float v1 = geluf(acc[mt][nn][1] + b1);
                float v2 = geluf(acc[mt][nn][2] + b0);
                float v3 = geluf(acc[mt][nn][3] + b1);
                #pragma unroll
                for (int k = 0; k < 3; k++) {
                    part[mt][0][k] += v0*fw0[k] + v1*fw1[k];
                    part[mt][1][k] += v2*fw0[k] + v3*fw1[k];
                }
            }
        }
        #pragma unroll
        for (int mt = 0; mt < 2; mt++)
            #pragma unroll
            for (int r = 0; r < 2; r++)
                #pragma unroll
                for (int k = 0; k < 3; k++) {
                    float v = part[mt][r][k];
                    v += __shfl_xor_sync(0xffffffffu, v, 1);
                    v += __shfl_xor_sync(0xffffffffu, v, 2);
                    part[mt][r][k] = v;
                }
        if (tg == 0) {
            const int slot = bn*2 + (nwarp >> 6);   // 0..31
            #pragma unroll
            for (int mt = 0; mt < 2; mt++)
                #pragma unroll
                for (int r = 0; r < 2; r++) {
                    const int bs = bm*BM + mwarp + mt*16 + r*8 + g;
                    #pragma unroll
                    for (int k = 0; k < 3; k++)
                        g_fs2[((size_t)bs*3 + k)*32 + slot] = part[mt][r][k];
                }
        }
    } else {
        #pragma unroll
        for (int nn = 0; nn < 8; nn++) {
            const int col = bn*BN + nwarp + nn*8 + tg*2;
            const float b0 = bias[col], b1 = bias[col+1];
            #pragma unroll
            for (int mt = 0; mt < 2; mt++) {
                const int row0 = bm*BM + mwarp + mt*16 + g;
                *(float2*)(C + (size_t)row0*NN + col)     = make_float2(acc[mt][nn][0] + b0, acc[mt][nn][1] + b1);
                *(float2*)(C + (size_t)(row0+8)*NN + col) = make_float2(acc[mt][nn][2] + b0, acc[mt][nn][3] + b1);
            }
        }
    }
}

// ---------------- stage 1: per-row slot sums + tanh -> g_fs -----------------
__global__ void fsum_kernel(const float* __restrict__ fb)
{
    int bs = blockIdx.x * blockDim.x + threadIdx.x;
    if (bs >= MM) return;
    const float4* p = (const float4*)(g_fs2 + (size_t)bs * 96);
    float out[3];
    #pragma unroll
    for (int k = 0; k < 3; k++) {
        float t0 = 0.f, t1 = 0.f;
        #pragma unroll
        for (int j = 0; j < 4; j++) {
            float4 v = p[k*8 + j];
            t0 += (v.x + v.y) + (v.z + v.w);
        }
        #pragma unroll
        for (int j = 4; j < 8; j++) {
            float4 v = p[k*8 + j];
            t1 += (v.x + v.y) + (v.z + v.w);
        }
        out[k] = tanhf(t0 + fb[k]) + tanhf(t1 + fb[k]);
    }
    g_fs[(size_t)bs*3+0] = out[0];
    g_fs[(size_t)bs*3+1] = out[1];
    g_fs[(size_t)bs*3+2] = out[2];
}

// ---------------- stage 2: per-batch mean -> w[b][k] ------------------------
__global__ void wreduce_kernel()
{
    const int b = blockIdx.x;
    float a0 = 0.f, a1 = 0.f, a2 = 0.f;
    for (int s = threadIdx.x; s < SS; s += blockDim.x) {
        size_t p = ((size_t)b * SS + s) * 3;
        a0 += g_fs[p+0]; a1 += g_fs[p+1]; a2 += g_fs[p+2];
    }
    #pragma unroll
    for (int off = 16; off; off >>= 1) {
        a0 += __shfl_xor_sync(0xffffffffu, a0, off);
        a1 += __shfl_xor_sync(0xffffffffu, a1, off);
        a2 += __shfl_xor_sync(0xffffffffu, a2, off);
    }
    __shared__ float red[32][3];
    int warp = threadIdx.x >> 5, lane = threadIdx.x & 31;
    if (lane == 0) { red[warp][0] = a0; red[warp][1] = a1; red[warp][2] = a2; }
    __syncthreads();
    if (threadIdx.x == 0) {
        float s0 = 0.f, s1 = 0.f, s2 = 0.f;
        const int nw = blockDim.x >> 5;
        for (int w = 0; w < nw; w++) { s0 += red[w][0]; s1 += red[w][1]; s2 += red[w][2]; }
        const float inv = 1.0f / (float)SS;
        g_w[b*3+0] = s0 * inv;
        g_w[b*3+1] = s1 * inv;
        g_w[b*3+2] = s2 * inv;
    }
}

// -------- kernel 5: gated conv * v, gelu -> y, 4 s-positions per thread -----
__global__ void convgate_kernel(const float* __restrict__ x)
{
    int idx = blockIdx.x * blockDim.x + threadIdx.x;
    if (idx >= BB * S4 * D4) return;
    int d4 = idx % D4;
    int g  = idx / D4;
    int s0 = (g & (S4 - 1)) * 4;
    int b  = g >> 9;
    size_t rowbase = ((size_t)(b*SS + s0))*DD + d4*4;

    float w0 = g_w[b*3+0], w1 = g_w[b*3+1], w2 = g_w[b*3+2];

    float c[6][4];
    #pragma unroll
    for (int i = 0; i < 6; i++) {
        int s = s0 + i - 2;
        if (s >= 0) {
            size_t p = rowbase + (ptrdiff_t)(i-2)*DD;
            __half2 p0 = *(const __half2*)(g_x2 + p);
            __half2 p1 = *(const __half2*)(g_x2 + p + 2);
            c[i][0] = __low2float(p0); c[i][1] = __high2float(p0);
            c[i][2] = __low2float(p1); c[i][3] = __high2float(p1);
        } else {
            c[i][0] = c[i][1] = c[i][2] = c[i][3] = 0.f;
        }
    }
    #pragma unroll
    for (int i = 0; i < 4; i++) {
        size_t p = rowbase + (size_t)i*DD;
        float4 v = *(const float4*)(x + p);
        const float vv[4] = {v.x, v.y, v.z, v.w};
        float o[4];
        #pragma unroll
        for (int q = 0; q < 4; q++)
            o[q] = geluf((c[i][q]*w0 + c[i+1][q]*w1 + c[i+2][q]*w2) * vv[q]);
        *(__half2*)(g_y + p)     = __floats2half2_rn(o[0], o[1]);
        *(__half2*)(g_y + p + 2) = __floats2half2_rn(o[2], o[3]);
    }
}

// ---------------- launcher ---------------------------------------------------
extern "C" void kernel_launch(void* const* d_in, const int* in_sizes, int n_in,
                              void* d_out, int out_size)
{
    const float* x       = (const float*)d_in[0];
    const float* short_w = (const float*)d_in[1];
    const float* short_b = (const float*)d_in[2];
    const float* proj_w  = (const float*)d_in[3];
    const float* proj_b  = (const float*)d_in[4];
    const float* filt_w  = (const float*)d_in[5];
    const float* filt_b  = (const float*)d_in[6];
    const float* out_w   = (const float*)d_in[7];
    const float* out_b   = (const float*)d_in[8];
    float* out = (float*)d_out;

    __half *px2, *py, *ppw, *pow_;
    cudaGetSymbolAddress((void**)&px2, g_x2);
    cudaGetSymbolAddress((void**)&py,  g_y);
    cudaGetSymbolAddress((void**)&ppw, g_pw);
    cudaGetSymbolAddress((void**)&pow_, g_ow);

    cudaFuncSetAttribute((const void*)gemm_h<1>, cudaFuncAttributeMaxDynamicSharedMemorySize, SMEM_BYTES);
    cudaFuncSetAttribute((const void*)gemm_h<0>, cudaFuncAttributeMaxDynamicSharedMemorySize, SMEM_BYTES);

    // 1. fused prologue: both weight converts + shortconv in one launch
    prep_kernel<<<12288, 256>>>(x, short_w, short_b, proj_w, out_w);

    // 2. fused: gelu(x2@proj_w + proj_b) folded with filt_w -> g_fs2
    dim3 ggrid(NN / BN, MM / BM);   // (16, 64)
    gemm_h<1><<<ggrid, 256, SMEM_BYTES>>>(px2, ppw, proj_b, nullptr, filt_w);

    // 3a. per-row slot sums + tanh (fully parallel)
    fsum_kernel<<<MM/256, 256>>>(filt_b);

    // 3b. per-batch mean -> w
    wreduce_kernel<<<BB, 1024>>>();

    // 4. y = gelu(conv(x2; w) * x) -> y fp16, 4 s-rows/thread
    convgate_kernel<<<(BB*S4*D4)/256, 256>>>(x);

    // 5. out = y @ out_w + out_b — fp32 out
    gemm_h<0><<<ggrid, 256, SMEM_BYTES>>>(py, pow_, out_b, out, nullptr);
}

// round 14
// speedup vs baseline: 1.0115x; 1.0115x over previous
#include <cuda_runtime.h>
#include <cuda_fp16.h>
#include <math.h>
#include <stdint.h>

#define BB 4
#define SS 2048
#define DD 2048
#define DI 1024
#define MM (BB*SS)      // 8192
#define KK DD
#define NN DD
#define D4 (DD/4)
#define S4 (SS/4)       // 512

// GEMM tiling: CTA 128x128, 8 warps (4M x 2N), warp tile 32x64, BKK=64, 3 stages
#define BM 128
#define BN 128
#define BKK 64
#define ASZ (BM*BKK)    // 8192 halves
#define BSZ (BKK*BN)    // 8192 halves
#define NSTAGE 3
#define STG_H (ASZ + BSZ)
#define SMEM_BYTES (NSTAGE*STG_H*2)    // 98304

// ---------------- scratch ---------------------------------------------------
__device__ __half g_x2[(size_t)MM*KK];
__device__ __half g_y [(size_t)MM*KK];
__device__ __half g_pw[(size_t)KK*NN];
__device__ __half g_ow[(size_t)KK*NN];
__device__ float g_fs2[(size_t)MM*3*32];
__device__ float g_fs [(size_t)MM*3];
__device__ float g_w [BB*3];

__device__ __forceinline__ float geluf(float v) {
    return 0.5f * v * (1.0f + erff(v * 0.70710678118654752f));
}
__device__ __forceinline__ uint32_t smem_u32(const void* p) {
    return (uint32_t)__cvta_generic_to_shared(p);
}

#define CP16(s, g) asm volatile("cp.async.cg.shared.global [%0], [%1], 16;\n" :: "r"(s), "l"(g))
#define CP_COMMIT() asm volatile("cp.async.commit_group;\n")
#define LDSM4(R0,R1,R2,R3,addr) \
    asm volatile("ldmatrix.sync.aligned.m8n8.x4.shared.b16 {%0,%1,%2,%3},[%4];" \
                 : "=r"(R0),"=r"(R1),"=r"(R2),"=r"(R3) : "r"(addr))
#define LDSM4T(R0,R1,R2,R3,addr) \
    asm volatile("ldmatrix.sync.aligned.m8n8.x4.trans.shared.b16 {%0,%1,%2,%3},[%4];" \
                 : "=r"(R0),"=r"(R1),"=r"(R2),"=r"(R3) : "r"(addr))
#define MMAH16816(D0,D1,D2,D3,A0,A1,A2,A3,B0,B1) \
    asm volatile("mma.sync.aligned.m16n8k16.row.col.f32.f16.f16.f32 " \
                 "{%0,%1,%2,%3},{%4,%5,%6,%7},{%8,%9},{%0,%1,%2,%3};" \
                 : "+f"(D0),"+f"(D1),"+f"(D2),"+f"(D3) \
                 : "r"(A0),"r"(A1),"r"(A2),"r"(A3),"r"(B0),"r"(B1))

// ------- fused prologue: convert proj_w, convert out_w, shortconv ----------
__global__ void prep_kernel(const float* __restrict__ x,
                            const float* __restrict__ sw,
                            const float* __restrict__ sb,
                            const float* __restrict__ pw,
                            const float* __restrict__ ow)
{
    const int blk = blockIdx.x;
    if (blk < 8192) {
        const float* src = (blk < 4096) ? pw : ow;
        __half* dst = (blk < 4096) ? g_pw : g_ow;
        int i = (blk & 4095) * 256 + threadIdx.x;
        size_t base = (size_t)i * 4;
        float4 v = *(const float4*)(src + base);
        *(__half2*)(dst + base)     = __floats2half2_rn(v.x, v.y);
        *(__half2*)(dst + base + 2) = __floats2half2_rn(v.z, v.w);
        return;
    }
    int idx = (blk - 8192) * 256 + threadIdx.x;
    int d4 = idx % D4;
    int g  = idx / D4;
    int s0 = (g & (S4 - 1)) * 4;
    int b  = g >> 9;
    int d  = d4 * 4;
    size_t rowbase = ((size_t)(b*SS + s0))*DD + d;

    float4 r[6];
    #pragma unroll
    for (int i = 0; i < 6; i++) {
        int s = s0 + i - 2;
        r[i] = (s >= 0) ? *(const float4*)(x + rowbase + (ptrdiff_t)(i-2)*DD)
                        : make_float4(0.f, 0.f, 0.f, 0.f);
    }
    float w0[4], w1[4], w2[4], bb[4];
    #pragma unroll
    for (int q = 0; q < 4; q++) {
        w0[q] = sw[(d+q)*3+0]; w1[q] = sw[(d+q)*3+1]; w2[q] = sw[(d+q)*3+2];
        bb[q] = sb[d+q];
    }
    #pragma unroll
    for (int i = 0; i < 4; i++) {
        const float cv[4] = {r[i+2].x, r[i+2].y, r[i+2].z, r[i+2].w};
        const float pv[4] = {r[i+1].x, r[i+1].y, r[i+1].z, r[i+1].w};
        const float qv[4] = {r[i].x,   r[i].y,   r[i].z,   r[i].w};
        float o[4];
        #pragma unroll
        for (int q = 0; q < 4; q++)
            o[q] = cv[q] + bb[q] + qv[q]*w0[q] + pv[q]*w1[q] + cv[q]*w2[q];
        size_t ob = rowbase + (size_t)i*DD;
        *(__half2*)(g_x2 + ob)     = __floats2half2_rn(o[0], o[1]);
        *(__half2*)(g_x2 + ob + 2) = __floats2half2_rn(o[2], o[3]);
    }
}

// --- fp16 GEMM: 128x128 tile, 8 warps (4Mx2N), 32x64 wtile, frag dbl-buf ---
template<int REDUCE>
__global__ void __launch_bounds__(256, 2)
gemm_h(const __half* __restrict__ A, const __half* __restrict__ B,
       const float* __restrict__ bias, float* __restrict__ C,
       const float* __restrict__ fw)
{
    extern __shared__ __half sm[];

    const int tid  = threadIdx.x;
    const int bm   = blockIdx.y, bn = blockIdx.x;
    const int warp = tid >> 5, lane = tid & 31;
    const int mwarp = (warp & 3) * 32;     // 4 warps in M
    const int nwarp = (warp >> 2) * 64;    // 2 warps in N

    const uint32_t base0 = smem_u32(sm);

    auto issue = [&](int stg, int t) {
        uint32_t aS = base0 + (uint32_t)stg*STG_H*2;
        uint32_t bS = aS + ASZ*2;
        const __half* gAt = A + (size_t)(bm*BM)*KK + (size_t)t*BKK;
        const __half* gBt = B + (size_t)((size_t)t*BKK)*NN + bn*BN;
        #pragma unroll
        for (int j = 0; j < 4; j++) {
            int idx = tid + 256*j;
            int row = idx >> 3, ch = idx & 7;
            uint32_t so = (uint32_t)row*128u + (uint32_t)(((ch ^ (row & 7)) << 4));
            CP16(aS + so, gAt + (size_t)row*KK + ch*8);
        }
        #pragma unroll
        for (int j = 0; j < 4; j++) {
            int idx = tid + 256*j;
            int row = idx >> 4, ch = idx & 15;
            uint32_t so = (uint32_t)row*256u + (uint32_t)(((ch ^ (row & 7)) << 4));
            CP16(bS + so, gBt + (size_t)row*NN + ch*8);
        }
        CP_COMMIT();
    };

    float acc[2][8][4];
    #pragma unroll
    for (int i = 0; i < 2; i++)
        #pragma unroll
        for (int j = 0; j < 8; j++)
            #pragma unroll
            for (int q = 0; q < 4; q++) acc[i][j][q] = 0.f;

    const int lr  = lane & 15;
    const int hc  = lane >> 4;
    const int swz = lr & 7;
    int rowA[2];
    rowA[0] = mwarp + lr;
    rowA[1] = mwarp + 16 + lr;
    const int ncbase = (warp >> 2) * 8;

    uint32_t af[2][2][4];     // [ks-buf][m-tile][frag]
    uint32_t bf[2][4];        // [p-buf][frag]

    const int NT = KK / BKK;               // 32
    issue(0, 0);
    issue(1, 1);

    for (int t = 0; t < NT; ++t) {
        const int stg = t % NSTAGE;
        asm volatile("cp.async.wait_group %0;\n" :: "n"(NSTAGE - 2));
        __syncthreads();
        if (t + 2 < NT) issue((t + 2) % NSTAGE, t + 2);

        const uint32_t aS = base0 + (uint32_t)stg*STG_H*2;
        const uint32_t bS = aS + ASZ*2;

        // preload ks=0 A frags + p=0 B frag
        {
            int chunk = hc ^ swz;
            LDSM4(af[0][0][0], af[0][0][1], af[0][0][2], af[0][0][3],
                  aS + (uint32_t)rowA[0]*128 + chunk*16);
            LDSM4(af[0][1][0], af[0][1][1], af[0][1][2], af[0][1][3],
                  aS + (uint32_t)rowA[1]*128 + chunk*16);
            int bchunk = (ncbase + hc) ^ swz;
            LDSM4T(bf[0][0], bf[0][1], bf[0][2], bf[0][3],
                   bS + (uint32_t)lr*256 + bchunk*16);
        }

        #pragma unroll
        for (int ks = 0; ks < 4; ks++) {
            const int krow = ks*16 + lr;
            const int cab = ks & 1;
            #pragma unroll
            for (int p = 0; p < 4; p++) {
                const int cb = p & 1, nb = cb ^ 1;
                if (p < 3) {
                    int chunk = (ncbase + 2*(p+1) + hc) ^ swz;
                    LDSM4T(bf[nb][0], bf[nb][1], bf[nb][2], bf[nb][3],
                           bS + (uint32_t)krow*256 + chunk*16);
                } else if (ks < 3) {
                    int achunk = (2*(ks+1) + hc) ^ swz;
                    LDSM4(af[cab^1][0][0], af[cab^1][0][1], af[cab^1][0][2], af[cab^1][0][3],
                          aS + (uint32_t)rowA[0]*128 + achunk*16);
                    LDSM4(af[cab^1][1][0], af[cab^1][1][1], af[cab^1][1][2], af[cab^1][1][3],
                          aS + (uint32_t)rowA[1]*128 + achunk*16);
                    int bchunk = (ncbase + hc) ^ swz;
                    LDSM4T(bf[nb][0], bf[nb][1], bf[nb][2], bf[nb][3],
                           bS + (uint32_t)(krow + 16)*256 + bchunk*16);
                }
                #pragma unroll
                for (int mt = 0; mt < 2; mt++) {
                    MMAH16816(acc[mt][2*p+0][0],acc[mt][2*p+0][1],acc[mt][2*p+0][2],acc[mt][2*p+0][3],
                              af[cab][mt][0],af[cab][mt][1],af[cab][mt][2],af[cab][mt][3],
                              bf[cb][0],bf[cb][1]);
                    MMAH16816(acc[mt][2*p+1][0],acc[mt][2*p+1][1],acc[mt][2*p+1][2],acc[mt][2*p+1][3],
                              af[cab][mt][0],af[cab][mt][1],af[cab][mt][2],af[cab][mt][3],
                              bf[cb][2],bf[cb][3]);
                }
            }
        }
    }

    // ---- epilogue ----
    const int g  = lane >> 2;
    const int tg = lane & 3;

    if (REDUCE) {
        float part[2][2][3];
        #pragma unroll
        for (int mt = 0; mt < 2; mt++)
            #pragma unroll
            for (int r = 0; r < 2; r++)
                #pragma unroll
                for (int k = 0; k < 3; k++) part[mt][r][k] = 0.f;

        #pragma unroll
        for (int nn = 0; nn < 8; nn++) {
            const int col = bn*BN + nwarp + nn*8 + tg*2;
            const float b0 = bias[col], b1 = bias[col+1];
            const int i0 = col & (DI-1);
            float fw0[3], fw1[3];
            #pragma unroll
            for (int k = 0; k < 3; k++) { fw0[k] = fw[i0*3+k]; fw1[k] = fw[(i0+1)*3+k]; }
            #pragma unroll
            for (int mt = 0; mt < 2; mt++) {
                float v0 = geluf(acc[mt][nn][0] + b0);
                float v1 = geluf(acc[mt][nn][1] + b1);
                float v2 = geluf(acc[mt][nn][2] + b0);
                float v3 = geluf(acc[mt][nn][3] + b1);
                #pragma unroll
                for (int k = 0; k < 3; k++) {
                    part[mt][0][k] += v0*fw0[k] + v1*fw1[k];
                    part[mt][1][k] += v2*fw0[k] + v3*fw1[k];
                }
            }
        }
        #pragma unroll
        for (int mt = 0; mt < 2; mt++)
            #pragma unroll
            for (int r = 0; r < 2; r++)
                #pragma unroll
                for (int k = 0; k < 3; k++) {
                    float v = part[mt][r][k];
                    v += __shfl_xor_sync(0xffffffffu, v, 1);
                    v += __shfl_xor_sync(0xffffffffu, v, 2);
                    part[mt][r][k] = v;
                }
        if (tg == 0) {
            const int slot = bn*2 + (nwarp >> 6);
            #pragma unroll
            for (int mt = 0; mt < 2; mt++)
                #pragma unroll
                for (int r = 0; r < 2; r++) {
                    const int bs = bm*BM + mwarp + mt*16 + r*8 + g;
                    #pragma unroll
                    for (int k = 0; k < 3; k++)
                        g_fs2[((size_t)bs*3 + k)*32 + slot] = part[mt][r][k];
                }
        }
    } else {
        #pragma unroll
        for (int nn = 0; nn < 8; nn++) {
            const int col = bn*BN + nwarp + nn*8 + tg*2;
            const float b0 = bias[col], b1 = bias[col+1];
            #pragma unroll
            for (int mt = 0; mt < 2; mt++) {
                const int row0 = bm*BM + mwarp + mt*16 + g;
                *(float2*)(C + (size_t)row0*NN + col)     = make_float2(acc[mt][nn][0] + b0, acc[mt][nn][1] + b1);
                *(float2*)(C + (size_t)(row0+8)*NN + col) = make_float2(acc[mt][nn][2] + b0, acc[mt][nn][3] + b1);
            }
        }
    }
}

// ---------------- stage 1: per-row slot sums + tanh -> g_fs -----------------
__global__ void fsum_kernel(const float* __restrict__ fb)
{
    int bs = blockIdx.x * blockDim.x + threadIdx.x;
    if (bs >= MM) return;
    const float4* p = (const float4*)(g_fs2 + (size_t)bs * 96);
    float out[3];
    #pragma unroll
    for (int k = 0; k < 3; k++) {
        float t0 = 0.f, t1 = 0.f;
        #pragma unroll
        for (int j = 0; j < 4; j++) {
            float4 v = p[k*8 + j];
            t0 += (v.x + v.y) + (v.z + v.w);
        }
        #pragma unroll
        for (int j = 4; j < 8; j++) {
            float4 v = p[k*8 + j];
            t1 += (v.x + v.y) + (v.z + v.w);
        }
        out[k] = tanhf(t0 + fb[k]) + tanhf(t1 + fb[k]);
    }
    g_fs[(size_t)bs*3+0] = out[0];
    g_fs[(size_t)bs*3+1] = out[1];
    g_fs[(size_t)bs*3+2] = out[2];
}

// ---------------- stage 2: per-batch mean -> w[b][k] ------------------------
__global__ void wreduce_kernel()
{
    const int b = blockIdx.x;
    float a0 = 0.f, a1 = 0.f, a2 = 0.f;
    for (int s = threadIdx.x; s < SS; s += blockDim.x) {
        size_t p = ((size_t)b * SS + s) * 3;
        a0 += g_fs[p+0]; a1 += g_fs[p+1]; a2 += g_fs[p+2];
    }
    #pragma unroll
    for (int off = 16; off; off >>= 1) {
        a0 += __shfl_xor_sync(0xffffffffu, a0, off);
        a1 += __shfl_xor_sync(0xffffffffu, a1, off);
        a2 += __shfl_xor_sync(0xffffffffu, a2, off);
    }
    __shared__ float red[32][3];
    int warp = threadIdx.x >> 5, lane = threadIdx.x & 31;
    if (lane == 0) { red[warp][0] = a0; red[warp][1] = a1; red[warp][2] = a2; }
    __syncthreads();
    if (threadIdx.x == 0) {
        float s0 = 0.f, s1 = 0.f, s2 = 0.f;
        const int nw = blockDim.x >> 5;
        for (int w = 0; w < nw; w++) { s0 += red[w][0]; s1 += red[w][1]; s2 += red[w][2]; }
        const float inv = 1.0f / (float)SS;
        g_w[b*3+0] = s0 * inv;
        g_w[b*3+1] = s1 * inv;
        g_w[b*3+2] = s2 * inv;
    }
}

// -------- kernel 5: gated conv * v, gelu -> y, 4 s-positions per thread -----
__global__ void convgate_kernel(const float* __restrict__ x)
{
    int idx = blockIdx.x * blockDim.x + threadIdx.x;
    if (idx >= BB * S4 * D4) return;
    int d4 = idx % D4;
    int g  = idx / D4;
    int s0 = (g & (S4 - 1)) * 4;
    int b  = g >> 9;
    size_t rowbase = ((size_t)(b*SS + s0))*DD + d4*4;

    float w0 = g_w[b*3+0], w1 = g_w[b*3+1], w2 = g_w[b*3+2];

    float c[6][4];
    #pragma unroll
    for (int i = 0; i < 6; i++) {
        int s = s0 + i - 2;
        if (s >= 0) {
            size_t p = rowbase + (ptrdiff_t)(i-2)*DD;
            __half2 p0 = *(const __half2*)(g_x2 + p);
            __half2 p1 = *(const __half2*)(g_x2 + p + 2);
            c[i][0] = __low2float(p0); c[i][1] = __high2float(p0);
            c[i][2] = __low2float(p1); c[i][3] = __high2float(p1);
        } else {
            c[i][0] = c[i][1] = c[i][2] = c[i][3] = 0.f;
        }
    }
    #pragma unroll
    for (int i = 0; i < 4; i++) {
        size_t p = rowbase + (size_t)i*DD;
        float4 v = *(const float4*)(x + p);
        const float vv[4] = {v.x, v.y, v.z, v.w};
        float o[4];
        #pragma unroll
        for (int q = 0; q < 4; q++)
            o[q] = geluf((c[i][q]*w0 + c[i+1][q]*w1 + c[i+2][q]*w2) * vv[q]);
        *(__half2*)(g_y + p)     = __floats2half2_rn(o[0], o[1]);
        *(__half2*)(g_y + p + 2) = __floats2half2_rn(o[2], o[3]);
    }
}

// ---------------- launcher ---------------------------------------------------
extern "C" void kernel_launch(void* const* d_in, const int* in_sizes, int n_in,
                              void* d_out, int out_size)
{
    const float* x       = (const float*)d_in[0];
    const float* short_w = (const float*)d_in[1];
    const float* short_b = (const float*)d_in[2];
    const float* proj_w  = (const float*)d_in[3];
    const float* proj_b  = (const float*)d_in[4];
    const float* filt_w  = (const float*)d_in[5];
    const float* filt_b  = (const float*)d_in[6];
    const float* out_w   = (const float*)d_in[7];
    const float* out_b   = (const float*)d_in[8];
    float* out = (float*)d_out;

    __half *px2, *py, *ppw, *pow_;
    cudaGetSymbolAddress((void**)&px2, g_x2);
    cudaGetSymbolAddress((void**)&py,  g_y);
    cudaGetSymbolAddress((void**)&ppw, g_pw);
    cudaGetSymbolAddress((void**)&pow_, g_ow);

    cudaFuncSetAttribute((const void*)gemm_h<1>, cudaFuncAttributeMaxDynamicSharedMemorySize, SMEM_BYTES);
    cudaFuncSetAttribute((const void*)gemm_h<0>, cudaFuncAttributeMaxDynamicSharedMemorySize, SMEM_BYTES);

    // 1. fused prologue
    prep_kernel<<<12288, 256>>>(x, short_w, short_b, proj_w, out_w);

    // 2. fused GEMM1 + filter fold
    dim3 ggrid(NN / BN, MM / BM);   // (16, 64)
    gemm_h<1><<<ggrid, 256, SMEM_BYTES>>>(px2, ppw, proj_b, nullptr, filt_w);

    // 3. filter reductions
    fsum_kernel<<<MM/256, 256>>>(filt_b);
    wreduce_kernel<<<BB, 1024>>>();

    // 4. gated conv + gelu
    convgate_kernel<<<(BB*S4*D4)/256, 256>>>(x);

    // 5. GEMM2
    gemm_h<0><<<ggrid, 256, SMEM_BYTES>>>(py, pow_, out_b, out, nullptr);
}

// round 15
// speedup vs baseline: 1.0166x; 1.0050x over previous
#include <cuda_runtime.h>
#include <cuda_fp16.h>
#include <math.h>
#include <stdint.h>

#define BB 4
#define SS 2048
#define DD 2048
#define DI 1024
#define MM (BB*SS)      // 8192
#define KK DD
#define NN DD
#define D4 (DD/4)
#define S4 (SS/4)       // 512

// GEMM tiling: CTA 128x128, 4 warps (2M x 2N), warp tile 64x64, BKK=64, 3 stages
#define BM 128
#define BN 128
#define BKK 64
#define ASZ (BM*BKK)    // 8192 halves
#define BSZ (BKK*BN)    // 8192 halves
#define NSTAGE 3
#define STG_H (ASZ + BSZ)
#define SMEM_BYTES (NSTAGE*STG_H*2)    // 98304

// ---------------- scratch ---------------------------------------------------
__device__ __half g_x2[(size_t)MM*KK];
__device__ __half g_y [(size_t)MM*KK];
__device__ __half g_pw[(size_t)KK*NN];
__device__ __half g_ow[(size_t)KK*NN];
__device__ float g_fs2[(size_t)MM*3*32];   // per-(row,k) partials x 32 column-groups
__device__ float g_fs [(size_t)MM*3];      // per-row tanh-summed filters
__device__ float g_w [BB*3];

__device__ __forceinline__ float geluf(float v) {
    return 0.5f * v * (1.0f + erff(v * 0.70710678118654752f));
}
__device__ __forceinline__ uint32_t smem_u32(const void* p) {
    return (uint32_t)__cvta_generic_to_shared(p);
}

#define CP16(s, g) asm volatile("cp.async.cg.shared.global [%0], [%1], 16;\n" :: "r"(s), "l"(g))
#define CP_COMMIT() asm volatile("cp.async.commit_group;\n")
#define LDSM4(R0,R1,R2,R3,addr) \
    asm volatile("ldmatrix.sync.aligned.m8n8.x4.shared.b16 {%0,%1,%2,%3},[%4];" \
                 : "=r"(R0),"=r"(R1),"=r"(R2),"=r"(R3) : "r"(addr))
#define LDSM4T(R0,R1,R2,R3,addr) \
    asm volatile("ldmatrix.sync.aligned.m8n8.x4.trans.shared.b16 {%0,%1,%2,%3},[%4];" \
                 : "=r"(R0),"=r"(R1),"=r"(R2),"=r"(R3) : "r"(addr))
#define MMAH16816(D0,D1,D2,D3,A0,A1,A2,A3,B0,B1) \
    asm volatile("mma.sync.aligned.m16n8k16.row.col.f32.f16.f16.f32 " \
                 "{%0,%1,%2,%3},{%4,%5,%6,%7},{%8,%9},{%0,%1,%2,%3};" \
                 : "+f"(D0),"+f"(D1),"+f"(D2),"+f"(D3) \
                 : "r"(A0),"r"(A1),"r"(A2),"r"(A3),"r"(B0),"r"(B1))

// ------- kernel 1: short conv + residual, 4 s-positions per thread ---------
__global__ void shortconv_kernel(const float* __restrict__ x,
                                 const float* __restrict__ sw,
                                 const float* __restrict__ sb)
{
    int idx = blockIdx.x * blockDim.x + threadIdx.x;
    if (idx >= BB * S4 * D4) return;
    int d4 = idx % D4;
    int g  = idx / D4;
    int s0 = (g & (S4 - 1)) * 4;
    int b  = g >> 9;           // S4 = 512
    int d  = d4 * 4;
    size_t rowbase = ((size_t)(b*SS + s0))*DD + d;

    float4 r[6];               // rows s0-2 .. s0+3
    #pragma unroll
    for (int i = 0; i < 6; i++) {
        int s = s0 + i - 2;
        r[i] = (s >= 0) ? *(const float4*)(x + rowbase + (ptrdiff_t)(i-2)*DD)
                        : make_float4(0.f, 0.f, 0.f, 0.f);
    }
    float w0[4], w1[4], w2[4], bb[4];
    #pragma unroll
    for (int q = 0; q < 4; q++) {
        w0[q] = sw[(d+q)*3+0]; w1[q] = sw[(d+q)*3+1]; w2[q] = sw[(d+q)*3+2];
        bb[q] = sb[d+q];
    }
    #pragma unroll
    for (int i = 0; i < 4; i++) {
        const float cv[4] = {r[i+2].x, r[i+2].y, r[i+2].z, r[i+2].w};
        const float pv[4] = {r[i+1].x, r[i+1].y, r[i+1].z, r[i+1].w};
        const float qv[4] = {r[i].x,   r[i].y,   r[i].z,   r[i].w};
        float o[4];
        #pragma unroll
        for (int q = 0; q < 4; q++)
            o[q] = cv[q] + bb[q] + qv[q]*w0[q] + pv[q]*w1[q] + cv[q]*w2[q];
        size_t ob = rowbase + (size_t)i*DD;
        *(__half2*)(g_x2 + ob)     = __floats2half2_rn(o[0], o[1]);
        *(__half2*)(g_x2 + ob + 2) = __floats2half2_rn(o[2], o[3]);
    }
}

// ---------------- weight conversion fp32 -> fp16 ----------------------------
__global__ void convert_half_kernel(const float* __restrict__ src,
                                    __half* __restrict__ dst, int n4)
{
    int i = blockIdx.x * blockDim.x + threadIdx.x;
    if (i >= n4) return;
    size_t base = (size_t)i * 4;
    float4 v = *(const float4*)(src + base);
    *(__half2*)(dst + base)     = __floats2half2_rn(v.x, v.y);
    *(__half2*)(dst + base + 2) = __floats2half2_rn(v.z, v.w);
}

// ---------------- fp16 tensor-core GEMM, 128x128 tile, 2 CTAs/SM -----------
template<int REDUCE>
__global__ void __launch_bounds__(128, 2)
gemm_h(const __half* __restrict__ A, const __half* __restrict__ B,
       const float* __restrict__ bias, float* __restrict__ C,
       const float* __restrict__ fw)
{
    extern __shared__ __half sm[];

    const int tid  = threadIdx.x;
    const int bm   = blockIdx.y, bn = blockIdx.x;
    const int warp = tid >> 5, lane = tid & 31;
    const int mwarp = (warp & 1) * 64;
    const int nwarp = (warp >> 1) * 64;

    const uint32_t base0 = smem_u32(sm);

    auto issue = [&](int stg, int t) {
        uint32_t aS = base0 + (uint32_t)stg*STG_H*2;
        uint32_t bS = aS + ASZ*2;
        const __half* gAt = A + (size_t)(bm*BM)*KK + (size_t)t*BKK;
        const __half* gBt = B + (size_t)((size_t)t*BKK)*NN + bn*BN;
        #pragma unroll
        for (int j = 0; j < 8; j++) {
            int idx = tid + 128*j;
            int row = idx >> 3, ch = idx & 7;
            uint32_t so = (uint32_t)row*128u + (uint32_t)(((ch ^ (row & 7)) << 4));
            CP16(aS + so, gAt + (size_t)row*KK + ch*8);
        }
        #pragma unroll
        for (int j = 0; j < 8; j++) {
            int idx = tid + 128*j;
            int row = idx >> 4, ch = idx & 15;
            uint32_t so = (uint32_t)row*256u + (uint32_t)(((ch ^ (row & 7)) << 4));
            CP16(bS + so, gBt + (size_t)row*NN + ch*8);
        }
        CP_COMMIT();
    };

    float acc[4][8][4];
    #pragma unroll
    for (int i = 0; i < 4; i++)
        #pragma unroll
        for (int j = 0; j < 8; j++)
            #pragma unroll
            for (int q = 0; q < 4; q++) acc[i][j][q] = 0.f;

    const int lr  = lane & 15;
    const int hc  = lane >> 4;
    const int swz = lr & 7;
    int rowA[4];
    #pragma unroll
    for (int mt = 0; mt < 4; mt++) rowA[mt] = mwarp + mt*16 + lr;
    const int ncbase = (warp >> 1) * 8;

    uint32_t af[2][4][4];
    uint32_t bf[2][4];

    const int NT = KK / BKK;               // 32
    issue(0, 0);
    issue(1, 1);

    for (int t = 0; t < NT; ++t) {
        const int stg = t % NSTAGE;
        asm volatile("cp.async.wait_group %0;\n" :: "n"(NSTAGE - 2));
        __syncthreads();
        if (t + 2 < NT) issue((t + 2) % NSTAGE, t + 2);

        const uint32_t aS = base0 + (uint32_t)stg*STG_H*2;
        const uint32_t bS = aS + ASZ*2;

        // preload ks=0 fragments
        {
            int chunk = hc ^ swz;
            #pragma unroll
            for (int mt = 0; mt < 4; mt++)
                LDSM4(af[0][mt][0], af[0][mt][1], af[0][mt][2], af[0][mt][3],
                      aS + (uint32_t)rowA[mt]*128 + chunk*16);
            int bchunk = (ncbase + hc) ^ swz;
            LDSM4T(bf[0][0], bf[0][1], bf[0][2], bf[0][3],
                   bS + (uint32_t)lr*256 + bchunk*16);
        }

        #pragma unroll
        for (int ks = 0; ks < 4; ks++) {
            const int krow = ks*16 + lr;
            const int cab = ks & 1;
            #pragma unroll
            for (int p = 0; p < 4; p++) {
                const int cb = p & 1, nb = cb ^ 1;
                if (p < 3) {
                    int chunk = (ncbase + 2*(p+1) + hc) ^ swz;
                    LDSM4T(bf[nb][0], bf[nb][1], bf[nb][2], bf[nb][3],
                           bS + (uint32_t)krow*256 + chunk*16);
                } else if (ks < 3) {
                    int achunk = (2*(ks+1) + hc) ^ swz;
                    #pragma unroll
                    for (int mt = 0; mt < 4; mt++)
                        LDSM4(af[cab^1][mt][0], af[cab^1][mt][1], af[cab^1][mt][2], af[cab^1][mt][3],
                              aS + (uint32_t)rowA[mt]*128 + achunk*16);
                    int bchunk = (ncbase + hc) ^ swz;
                    LDSM4T(bf[nb][0], bf[nb][1], bf[nb][2], bf[nb][3],
                           bS + (uint32_t)(krow + 16)*256 + bchunk*16);
                }
                #pragma unroll
                for (int mt = 0; mt < 4; mt++) {
                    MMAH16816(acc[mt][2*p+0][0],acc[mt][2*p+0][1],acc[mt][2*p+0][2],acc[mt][2*p+0][3],
                              af[cab][mt][0],af[cab][mt][1],af[cab][mt][2],af[cab][mt][3],
                              bf[cb][0],bf[cb][1]);
                    MMAH16816(acc[mt][2*p+1][0],acc[mt][2*p+1][1],acc[mt][2*p+1][2],acc[mt][2*p+1][3],
                              af[cab][mt][0],af[cab][mt][1],af[cab][mt][2],af[cab][mt][3],
                              bf[cb][2],bf[cb][3]);
                }
            }
        }
    }

    // ---- epilogue ----
    const int g  = lane >> 2;
    const int tg = lane & 3;

    if (REDUCE) {
        float part[4][2][3];
        #pragma unroll
        for (int mt = 0; mt < 4; mt++)
            #pragma unroll
            for (int r = 0; r < 2; r++)
                #pragma unroll
                for (int k = 0; k < 3; k++) part[mt][r][k] = 0.f;

        #pragma unroll
        for (int nn = 0; nn < 8; nn++) {
            const int col = bn*BN + nwarp + nn*8 + tg*2;
            const float b0 = bias[col], b1 = bias[col+1];
            const int i0 = col & (DI-1);
            float fw0[3], fw1[3];
            #pragma unroll
            for (int k = 0; k < 3; k++) { fw0[k] = fw[i0*3+k]; fw1[k] = fw[(i0+1)*3+k]; }
            #pragma unroll
            for (int mt = 0; mt < 4; mt++) {
                float v0 = geluf(acc[mt][nn][0] + b0);
                float v1 = geluf(acc[mt][nn][1] + b1);
                float v2 = geluf(acc[mt][nn][2] + b0);
                float v3 = geluf(acc[mt][nn][3] + b1);
                #pragma unroll
                for (int k = 0; k < 3; k++) {
                    part[mt][0][k] += v0*fw0[k] + v1*fw1[k];
                    part[mt][1][k] += v2*fw0[k] + v3*fw1[k];
                }
            }
        }
        #pragma unroll
        for (int mt = 0; mt < 4; mt++)
            #pragma unroll
            for (int r = 0; r < 2; r++)
                #pragma unroll
                for (int k = 0; k < 3; k++) {
                    float v = part[mt][r][k];
                    v += __shfl_xor_sync(0xffffffffu, v, 1);
                    v += __shfl_xor_sync(0xffffffffu, v, 2);
                    part[mt][r][k] = v;
                }
        if (tg == 0) {
            const int slot = bn*2 + (nwarp >> 6);   // 0..31
            #pragma unroll
            for (int mt = 0; mt < 4; mt++)
                #pragma unroll
                for (int r = 0; r < 2; r++) {
                    const int bs = bm*BM + mwarp + mt*16 + r*8 + g;
                    #pragma unroll
                    for (int k = 0; k < 3; k++)
                        g_fs2[((size_t)bs*3 + k)*32 + slot] = part[mt][r][k];
                }
        }
    } else {
        #pragma unroll
        for (int nn = 0; nn < 8; nn++) {
            const int col = bn*BN + nwarp + nn*8 + tg*2;
            const float b0 = bias[col], b1 = bias[col+1];
            #pragma unroll
            for (int mt = 0; mt < 4; mt++) {
                const int row0 = bm*BM + mwarp + mt*16 + g;
                *(float2*)(C + (size_t)row0*NN + col)     = make_float2(acc[mt][nn][0] + b0, acc[mt][nn][1] + b1);
                *(float2*)(C + (size_t)(row0+8)*NN + col) = make_float2(acc[mt][nn][2] + b0, acc[mt][nn][3] + b1);
            }
        }
    }
}

// ---------------- stage 1: per-row slot sums + tanh -> g_fs -----------------
__global__ void fsum_kernel(const float* __restrict__ fb)
{
    int bs = blockIdx.x * blockDim.x + threadIdx.x;
    if (bs >= MM) return;
    const float4* p = (const float4*)(g_fs2 + (size_t)bs * 96);
    float out[3];
    #pragma unroll
    for (int k = 0; k < 3; k++) {
        float t0 = 0.f, t1 = 0.f;
        #pragma unroll
        for (int j = 0; j < 4; j++) {
            float4 v = p[k*8 + j];
            t0 += (v.x + v.y) + (v.z + v.w);
        }
        #pragma unroll
        for (int j = 4; j < 8; j++) {
            float4 v = p[k*8 + j];
            t1 += (v.x + v.y) + (v.z + v.w);
        }
        out[k] = tanhf(t0 + fb[k]) + tanhf(t1 + fb[k]);
    }
    g_fs[(size_t)bs*3+0] = out[0];
    g_fs[(size_t)bs*3+1] = out[1];
    g_fs[(size_t)bs*3+2] = out[2];
}

// ---------------- stage 2: per-batch mean -> w[b][k] ------------------------
__global__ void wreduce_kernel()
{
    const int b = blockIdx.x;
    float a0 = 0.f, a1 = 0.f, a2 = 0.f;
    for (int s = threadIdx.x; s < SS; s += blockDim.x) {
        size_t p = ((size_t)b * SS + s) * 3;
        a0 += g_fs[p+0]; a1 += g_fs[p+1]; a2 += g_fs[p+2];
    }
    #pragma unroll
    for (int off = 16; off; off >>= 1) {
        a0 += __shfl_xor_sync(0xffffffffu, a0, off);
        a1 += __shfl_xor_sync(0xffffffffu, a1, off);
        a2 += __shfl_xor_sync(0xffffffffu, a2, off);
    }
    __shared__ float red[32][3];
    int warp = threadIdx.x >> 5, lane = threadIdx.x & 31;
    if (lane == 0) { red[warp][0] = a0; red[warp][1] = a1; red[warp][2] = a2; }
    __syncthreads();
    if (threadIdx.x == 0) {
        float s0 = 0.f, s1 = 0.f, s2 = 0.f;
        const int nw = blockDim.x >> 5;
        for (int w = 0; w < nw; w++) { s0 += red[w][0]; s1 += red[w][1]; s2 += red[w][2]; }
        const float inv = 1.0f / (float)SS;
        g_w[b*3+0] = s0 * inv;
        g_w[b*3+1] = s1 * inv;
        g_w[b*3+2] = s2 * inv;
    }
}

// -------- kernel 5: gated conv * v, gelu -> y, 4 s-positions per thread -----
__global__ void convgate_kernel(const float* __restrict__ x)
{
    int idx = blockIdx.x * blockDim.x + threadIdx.x;
    if (idx >= BB * S4 * D4) return;
    int d4 = idx % D4;
    int g  = idx / D4;
    int s0 = (g & (S4 - 1)) * 4;
    int b  = g >> 9;
    size_t rowbase = ((size_t)(b*SS + s0))*DD + d4*4;

    float w0 = g_w[b*3+0], w1 = g_w[b*3+1], w2 = g_w[b*3+2];

    float c[6][4];             // x2 rows s0-2 .. s0+3
    #pragma unroll
    for (int i = 0; i < 6; i++) {
        int s = s0 + i - 2;
        if (s >= 0) {
            size_t p = rowbase + (ptrdiff_t)(i-2)*DD;
            __half2 p0 = *(const __half2*)(g_x2 + p);
            __half2 p1 = *(const __half2*)(g_x2 + p + 2);
            c[i][0] = __low2float(p0); c[i][1] = __high2float(p0);
            c[i][2] = __low2float(p1); c[i][3] = __high2float(p1);
        } else {
            c[i][0] = c[i][1] = c[i][2] = c[i][3] = 0.f;
        }
    }
    #pragma unroll
    for (int i = 0; i < 4; i++) {
        size_t p = rowbase + (size_t)i*DD;
        float4 v = *(const float4*)(x + p);
        const float vv[4] = {v.x, v.y, v.z, v.w};
        float o[4];
        #pragma unroll
        for (int q = 0; q < 4; q++)
            o[q] = geluf((c[i][q]*w0 + c[i+1][q]*w1 + c[i+2][q]*w2) * vv[q]);
        *(__half2*)(g_y + p)     = __floats2half2_rn(o[0], o[1]);
        *(__half2*)(g_y + p + 2) = __floats2half2_rn(o[2], o[3]);
    }
}

// ---------------- launcher ---------------------------------------------------
extern "C" void kernel_launch(void* const* d_in, const int* in_sizes, int n_in,
                              void* d_out, int out_size)
{
    const float* x       = (const float*)d_in[0];
    const float* short_w = (const float*)d_in[1];
    const float* short_b = (const float*)d_in[2];
    const float* proj_w  = (const float*)d_in[3];
    const float* proj_b  = (const float*)d_in[4];
    const float* filt_w  = (const float*)d_in[5];
    const float* filt_b  = (const float*)d_in[6];
    const float* out_w   = (const float*)d_in[7];
    const float* out_b   = (const float*)d_in[8];
    float* out = (float*)d_out;

    __half *px2, *py, *ppw, *pow_;
    cudaGetSymbolAddress((void**)&px2, g_x2);
    cudaGetSymbolAddress((void**)&py,  g_y);
    cudaGetSymbolAddress((void**)&ppw, g_pw);
    cudaGetSymbolAddress((void**)&pow_, g_ow);

    cudaFuncSetAttribute((const void*)gemm_h<1>, cudaFuncAttributeMaxDynamicSharedMemorySize, SMEM_BYTES);
    cudaFuncSetAttribute((const void*)gemm_h<0>, cudaFuncAttributeMaxDynamicSharedMemorySize, SMEM_BYTES);

    const int sthreads = 256;
    const int sblocks  = (BB * S4 * D4 + sthreads - 1) / sthreads;   // 4096

    // weight conversions
    {
        int n4 = (KK * NN) / 4;
        int blocks = (n4 + 255) / 256;
        convert_half_kernel<<<blocks, 256>>>(proj_w, ppw, n4);
        convert_half_kernel<<<blocks, 256>>>(out_w,  pow_, n4);
    }

    // 1. short conv residual -> x2 (fp16), 4 s-rows/thread
    shortconv_kernel<<<sblocks, sthreads>>>(x, short_w, short_b);

    // 2. fused: gelu(x2@proj_w + proj_b) folded with filt_w -> g_fs2
    dim3 ggrid(NN / BN, MM / BM);   // (16, 64)
    gemm_h<1><<<ggrid, 128, SMEM_BYTES>>>(px2, ppw, proj_b, nullptr, filt_w);

    // 3a. per-row slot sums + tanh (fully parallel)
    fsum_kernel<<<MM/256, 256>>>(filt_b);

    // 3b. per-batch mean -> w
    wreduce_kernel<<<BB, 1024>>>();

    // 4. y = gelu(conv(x2; w) * x) -> y fp16, 4 s-rows/thread
    convgate_kernel<<<sblocks, sthreads>>>(x);

    // 5. out = y @ out_w + out_b — fp32 out
    gemm_h<0><<<ggrid, 128, SMEM_BYTES>>>(py, pow_, out_b, out, nullptr);
}

// round 16
// speedup vs baseline: 1.0211x; 1.0044x over previous
#include <cuda_runtime.h>
#include <cuda_fp16.h>
#include <math.h>
#include <stdint.h>

#define BB 4
#define SS 2048
#define DD 2048
#define DI 1024
#define MM (BB*SS)      // 8192
#define KK DD
#define NN DD
#define D4 (DD/4)
#define S4 (SS/4)       // 512

// GEMM tiling: CTA 128x128, 4 warps (2M x 2N), warp tile 64x64, BKK=64, 3 stages
#define BM 128
#define BN 128
#define BKK 64
#define ASZ (BM*BKK)    // 8192 halves
#define BSZ (BKK*BN)    // 8192 halves
#define NSTAGE 3
#define STG_H (ASZ + BSZ)
#define SMEM_BYTES (NSTAGE*STG_H*2)    // 98304

// ---------------- scratch ---------------------------------------------------
__device__ __half g_x2[(size_t)MM*KK];
__device__ __half g_y [(size_t)MM*KK];
__device__ __half g_pw[(size_t)KK*NN];
__device__ __half g_ow[(size_t)KK*NN];
__device__ float g_fs2[(size_t)MM*3*32];   // per-(row,k) partials x 32 column-groups
__device__ float g_wpart[32*3];            // per-fsum-block partial sums

__device__ __forceinline__ float geluf(float v) {
    return 0.5f * v * (1.0f + erff(v * 0.70710678118654752f));
}
__device__ __forceinline__ uint32_t smem_u32(const void* p) {
    return (uint32_t)__cvta_generic_to_shared(p);
}

#define CP16(s, g) asm volatile("cp.async.cg.shared.global [%0], [%1], 16;\n" :: "r"(s), "l"(g))
#define CP_COMMIT() asm volatile("cp.async.commit_group;\n")
#define LDSM4(R0,R1,R2,R3,addr) \
    asm volatile("ldmatrix.sync.aligned.m8n8.x4.shared.b16 {%0,%1,%2,%3},[%4];" \
                 : "=r"(R0),"=r"(R1),"=r"(R2),"=r"(R3) : "r"(addr))
#define LDSM4T(R0,R1,R2,R3,addr) \
    asm volatile("ldmatrix.sync.aligned.m8n8.x4.trans.shared.b16 {%0,%1,%2,%3},[%4];" \
                 : "=r"(R0),"=r"(R1),"=r"(R2),"=r"(R3) : "r"(addr))
#define MMAH16816(D0,D1,D2,D3,A0,A1,A2,A3,B0,B1) \
    asm volatile("mma.sync.aligned.m16n8k16.row.col.f32.f16.f16.f32 " \
                 "{%0,%1,%2,%3},{%4,%5,%6,%7},{%8,%9},{%0,%1,%2,%3};" \
                 : "+f"(D0),"+f"(D1),"+f"(D2),"+f"(D3) \
                 : "r"(A0),"r"(A1),"r"(A2),"r"(A3),"r"(B0),"r"(B1))

// ------- kernel 1: short conv + residual, 4 s-positions per thread ---------
__global__ void shortconv_kernel(const float* __restrict__ x,
                                 const float* __restrict__ sw,
                                 const float* __restrict__ sb)
{
    int idx = blockIdx.x * blockDim.x + threadIdx.x;
    if (idx >= BB * S4 * D4) return;
    int d4 = idx % D4;
    int g  = idx / D4;
    int s0 = (g & (S4 - 1)) * 4;
    int b  = g >> 9;           // S4 = 512
    int d  = d4 * 4;
    size_t rowbase = ((size_t)(b*SS + s0))*DD + d;

    float4 r[6];               // rows s0-2 .. s0+3
    #pragma unroll
    for (int i = 0; i < 6; i++) {
        int s = s0 + i - 2;
        r[i] = (s >= 0) ? *(const float4*)(x + rowbase + (ptrdiff_t)(i-2)*DD)
                        : make_float4(0.f, 0.f, 0.f, 0.f);
    }
    float w0[4], w1[4], w2[4], bb[4];
    #pragma unroll
    for (int q = 0; q < 4; q++) {
        w0[q] = sw[(d+q)*3+0]; w1[q] = sw[(d+q)*3+1]; w2[q] = sw[(d+q)*3+2];
        bb[q] = sb[d+q];
    }
    #pragma unroll
    for (int i = 0; i < 4; i++) {
        const float cv[4] = {r[i+2].x, r[i+2].y, r[i+2].z, r[i+2].w};
        const float pv[4] = {r[i+1].x, r[i+1].y, r[i+1].z, r[i+1].w};
        const float qv[4] = {r[i].x,   r[i].y,   r[i].z,   r[i].w};
        float o[4];
        #pragma unroll
        for (int q = 0; q < 4; q++)
            o[q] = cv[q] + bb[q] + qv[q]*w0[q] + pv[q]*w1[q] + cv[q]*w2[q];
        size_t ob = rowbase + (size_t)i*DD;
        *(__half2*)(g_x2 + ob)     = __floats2half2_rn(o[0], o[1]);
        *(__half2*)(g_x2 + ob + 2) = __floats2half2_rn(o[2], o[3]);
    }
}

// ---------------- weight conversion fp32 -> fp16 ----------------------------
__global__ void convert_half_kernel(const float* __restrict__ src,
                                    __half* __restrict__ dst, int n4)
{
    int i = blockIdx.x * blockDim.x + threadIdx.x;
    if (i >= n4) return;
    size_t base = (size_t)i * 4;
    float4 v = *(const float4*)(src + base);
    *(__half2*)(dst + base)     = __floats2half2_rn(v.x, v.y);
    *(__half2*)(dst + base + 2) = __floats2half2_rn(v.z, v.w);
}

// ---------------- fp16 tensor-core GEMM, 128x128 tile, 2 CTAs/SM -----------
template<int REDUCE>
__global__ void __launch_bounds__(128, 2)
gemm_h(const __half* __restrict__ A, const __half* __restrict__ B,
       const float* __restrict__ bias, float* __restrict__ C,
       const float* __restrict__ fw)
{
    extern __shared__ __half sm[];

    const int tid  = threadIdx.x;
    const int bm   = blockIdx.y, bn = blockIdx.x;
    const int warp = tid >> 5, lane = tid & 31;
    const int mwarp = (warp & 1) * 64;
    const int nwarp = (warp >> 1) * 64;

    const uint32_t base0 = smem_u32(sm);

    auto issue = [&](int stg, int t) {
        uint32_t aS = base0 + (uint32_t)stg*STG_H*2;
        uint32_t bS = aS + ASZ*2;
        const __half* gAt = A + (size_t)(bm*BM)*KK + (size_t)t*BKK;
        const __half* gBt = B + (size_t)((size_t)t*BKK)*NN + bn*BN;
        #pragma unroll
        for (int j = 0; j < 8; j++) {
            int idx = tid + 128*j;
            int row = idx >> 3, ch = idx & 7;
            uint32_t so = (uint32_t)row*128u + (uint32_t)(((ch ^ (row & 7)) << 4));
            CP16(aS + so, gAt + (size_t)row*KK + ch*8);
        }
        #pragma unroll
        for (int j = 0; j < 8; j++) {
            int idx = tid + 128*j;
            int row = idx >> 4, ch = idx & 15;
            uint32_t so = (uint32_t)row*256u + (uint32_t)(((ch ^ (row & 7)) << 4));
            CP16(bS + so, gBt + (size_t)row*NN + ch*8);
        }
        CP_COMMIT();
    };

    float acc[4][8][4];
    #pragma unroll
    for (int i = 0; i < 4; i++)
        #pragma unroll
        for (int j = 0; j < 8; j++)
            #pragma unroll
            for (int q = 0; q < 4; q++) acc[i][j][q] = 0.f;

    const int lr  = lane & 15;
    const int hc  = lane >> 4;
    const int swz = lr & 7;
    int rowA[4];
    #pragma unroll
    for (int mt = 0; mt < 4; mt++) rowA[mt] = mwarp + mt*16 + lr;
    const int ncbase = (warp >> 1) * 8;

    uint32_t af[2][4][4];
    uint32_t bf[2][4];

    const int NT = KK / BKK;               // 32
    issue(0, 0);
    issue(1, 1);

    for (int t = 0; t < NT; ++t) {
        const int stg = t % NSTAGE;
        asm volatile("cp.async.wait_group %0;\n" :: "n"(NSTAGE - 2));
        __syncthreads();
        if (t + 2 < NT) issue((t + 2) % NSTAGE, t + 2);

        const uint32_t aS = base0 + (uint32_t)stg*STG_H*2;
        const uint32_t bS = aS + ASZ*2;

        // preload ks=0 fragments
        {
            int chunk = hc ^ swz;
            #pragma unroll
            for (int mt = 0; mt < 4; mt++)
                LDSM4(af[0][mt][0], af[0][mt][1], af[0][mt][2], af[0][mt][3],
                      aS + (uint32_t)rowA[mt]*128 + chunk*16);
            int bchunk = (ncbase + hc) ^ swz;
            LDSM4T(bf[0][0], bf[0][1], bf[0][2], bf[0][3],
                   bS + (uint32_t)lr*256 + bchunk*16);
        }

        #pragma unroll
        for (int ks = 0; ks < 4; ks++) {
            const int krow = ks*16 + lr;
            const int cab = ks & 1;
            #pragma unroll
            for (int p = 0; p < 4; p++) {
                const int cb = p & 1, nb = cb ^ 1;
                if (p < 3) {
                    int chunk = (ncbase + 2*(p+1) + hc) ^ swz;
                    LDSM4T(bf[nb][0], bf[nb][1], bf[nb][2], bf[nb][3],
                           bS + (uint32_t)krow*256 + chunk*16);
                } else if (ks < 3) {
                    int achunk = (2*(ks+1) + hc) ^ swz;
                    #pragma unroll
                    for (int mt = 0; mt < 4; mt++)
                        LDSM4(af[cab^1][mt][0], af[cab^1][mt][1], af[cab^1][mt][2], af[cab^1][mt][3],
                              aS + (uint32_t)rowA[mt]*128 + achunk*16);
                    int bchunk = (ncbase + hc) ^ swz;
                    LDSM4T(bf[nb][0], bf[nb][1], bf[nb][2], bf[nb][3],
                           bS + (uint32_t)(krow + 16)*256 + bchunk*16);
                }
                #pragma unroll
                for (int mt = 0; mt < 4; mt++) {
                    MMAH16816(acc[mt][2*p+0][0],acc[mt][2*p+0][1],acc[mt][2*p+0][2],acc[mt][2*p+0][3],
                              af[cab][mt][0],af[cab][mt][1],af[cab][mt][2],af[cab][mt][3],
                              bf[cb][0],bf[cb][1]);
                    MMAH16816(acc[mt][2*p+1][0],acc[mt][2*p+1][1],acc[mt][2*p+1][2],acc[mt][2*p+1][3],
                              af[cab][mt][0],af[cab][mt][1],af[cab][mt][2],af[cab][mt][3],
                              bf[cb][2],bf[cb][3]);
                }
            }
        }
    }

    // ---- epilogue ----
    const int g  = lane >> 2;
    const int tg = lane & 3;

    if (REDUCE) {
        float part[4][2][3];
        #pragma unroll
        for (int mt = 0; mt < 4; mt++)
            #pragma unroll
            for (int r = 0; r < 2; r++)
                #pragma unroll
                for (int k = 0; k < 3; k++) part[mt][r][k] = 0.f;

        #pragma unroll
        for (int nn = 0; nn < 8; nn++) {
            const int col = bn*BN + nwarp + nn*8 + tg*2;
            const float b0 = bias[col], b1 = bias[col+1];
            const int i0 = col & (DI-1);
            float fw0[3], fw1[3];
            #pragma unroll
            for (int k = 0; k < 3; k++) { fw0[k] = fw[i0*3+k]; fw1[k] = fw[(i0+1)*3+k]; }
            #pragma unroll
            for (int mt = 0; mt < 4; mt++) {
                float v0 = geluf(acc[mt][nn][0] + b0);
                float v1 = geluf(acc[mt][nn][1] + b1);
                float v2 = geluf(acc[mt][nn][2] + b0);
                float v3 = geluf(acc[mt][nn][3] + b1);
                #pragma unroll
                for (int k = 0; k < 3; k++) {
                    part[mt][0][k] += v0*fw0[k] + v1*fw1[k];
                    part[mt][1][k] += v2*fw0[k] + v3*fw1[k];
                }
            }
        }
        #pragma unroll
        for (int mt = 0; mt < 4; mt++)
            #pragma unroll
            for (int r = 0; r < 2; r++)
                #pragma unroll
                for (int k = 0; k < 3; k++) {
                    float v = part[mt][r][k];
                    v += __shfl_xor_sync(0xffffffffu, v, 1);
                    v += __shfl_xor_sync(0xffffffffu, v, 2);
                    part[mt][r][k] = v;
                }
        if (tg == 0) {
            const int slot = bn*2 + (nwarp >> 6);   // 0..31
            #pragma unroll
            for (int mt = 0; mt < 4; mt++)
                #pragma unroll
                for (int r = 0; r < 2; r++) {
                    const int bs = bm*BM + mwarp + mt*16 + r*8 + g;
                    #pragma unroll
                    for (int k = 0; k < 3; k++)
                        g_fs2[((size_t)bs*3 + k)*32 + slot] = part[mt][r][k];
                }
        }
    } else {
        #pragma unroll
        for (int nn = 0; nn < 8; nn++) {
            const int col = bn*BN + nwarp + nn*8 + tg*2;
            const float b0 = bias[col], b1 = bias[col+1];
            #pragma unroll
            for (int mt = 0; mt < 4; mt++) {
                const int row0 = bm*BM + mwarp + mt*16 + g;
                *(float2*)(C + (size_t)row0*NN + col)     = make_float2(acc[mt][nn][0] + b0, acc[mt][nn][1] + b1);
                *(float2*)(C + (size_t)(row0+8)*NN + col) = make_float2(acc[mt][nn][2] + b0, acc[mt][nn][3] + b1);
            }
        }
    }
}

// ---- stage 1: per-row slot sums + tanh, then block partial -> g_wpart ------
// grid = 32 blocks x 256 threads; each block covers 256 consecutive rows,
// all within one batch (2048 % 256 == 0).
__global__ void fsum_kernel(const float* __restrict__ fb)
{
    int bs = blockIdx.x * blockDim.x + threadIdx.x;
    const float4* p = (const float4*)(g_fs2 + (size_t)bs * 96);
    float out[3];
    #pragma unroll
    for (int k = 0; k < 3; k++) {
        float t0 = 0.f, t1 = 0.f;
        #pragma unroll
        for (int j = 0; j < 4; j++) {
            float4 v = p[k*8 + j];
            t0 += (v.x + v.y) + (v.z + v.w);
        }
        #pragma unroll
        for (int j = 4; j < 8; j++) {
            float4 v = p[k*8 + j];
            t1 += (v.x + v.y) + (v.z + v.w);
        }
        out[k] = tanhf(t0 + fb[k]) + tanhf(t1 + fb[k]);
    }
    // block reduction of out[k] over the 256 rows
    #pragma unroll
    for (int off = 16; off; off >>= 1)
        #pragma unroll
        for (int k = 0; k < 3; k++)
            out[k] += __shfl_xor_sync(0xffffffffu, out[k], off);

    __shared__ float red[8][3];
    int warp = threadIdx.x >> 5, lane = threadIdx.x & 31;
    if (lane == 0) { red[warp][0] = out[0]; red[warp][1] = out[1]; red[warp][2] = out[2]; }
    __syncthreads();
    if (threadIdx.x == 0) {
        float s0 = 0.f, s1 = 0.f, s2 = 0.f;
        #pragma unroll
        for (int w = 0; w < 8; w++) { s0 += red[w][0]; s1 += red[w][1]; s2 += red[w][2]; }
        g_wpart[blockIdx.x*3+0] = s0;
        g_wpart[blockIdx.x*3+1] = s1;
        g_wpart[blockIdx.x*3+2] = s2;
    }
}

// -------- kernel 5: gated conv * v, gelu -> y; computes w inline ------------
__global__ void convgate_kernel(const float* __restrict__ x)
{
    int idx = blockIdx.x * blockDim.x + threadIdx.x;
    if (idx >= BB * S4 * D4) return;
    int d4 = idx % D4;
    int g  = idx / D4;
    int s0 = (g & (S4 - 1)) * 4;
    int b  = g >> 9;
    size_t rowbase = ((size_t)(b*SS + s0))*DD + d4*4;

    // w[b][k] = (sum of 8 block partials) / SS  — fixed-order, deterministic
    float w0 = 0.f, w1 = 0.f, w2 = 0.f;
    #pragma unroll
    for (int j = 0; j < 8; j++) {
        const float* p = g_wpart + (b*8 + j)*3;
        w0 += p[0]; w1 += p[1]; w2 += p[2];
    }
    const float inv = 1.0f / (float)SS;
    w0 *= inv; w1 *= inv; w2 *= inv;

    float c[6][4];             // x2 rows s0-2 .. s0+3
    #pragma unroll
    for (int i = 0; i < 6; i++) {
        int s = s0 + i - 2;
        if (s >= 0) {
            size_t p = rowbase + (ptrdiff_t)(i-2)*DD;
            __half2 p0 = *(const __half2*)(g_x2 + p);
            __half2 p1 = *(const __half2*)(g_x2 + p + 2);
            c[i][0] = __low2float(p0); c[i][1] = __high2float(p0);
            c[i][2] = __low2float(p1); c[i][3] = __high2float(p1);
        } else {
            c[i][0] = c[i][1] = c[i][2] = c[i][3] = 0.f;
        }
    }
    #pragma unroll
    for (int i = 0; i < 4; i++) {
        size_t p = rowbase + (size_t)i*DD;
        float4 v = *(const float4*)(x + p);
        const float vv[4] = {v.x, v.y, v.z, v.w};
        float o[4];
        #pragma unroll
        for (int q = 0; q < 4; q++)
            o[q] = geluf((c[i][q]*w0 + c[i+1][q]*w1 + c[i+2][q]*w2) * vv[q]);
        *(__half2*)(g_y + p)     = __floats2half2_rn(o[0], o[1]);
        *(__half2*)(g_y + p + 2) = __floats2half2_rn(o[2], o[3]);
    }
}

// ---------------- launcher ---------------------------------------------------
extern "C" void kernel_launch(void* const* d_in, const int* in_sizes, int n_in,
                              void* d_out, int out_size)
{
    const float* x       = (const float*)d_in[0];
    const float* short_w = (const float*)d_in[1];
    const float* short_b = (const float*)d_in[2];
    const float* proj_w  = (const float*)d_in[3];
    const float* proj_b  = (const float*)d_in[4];
    const float* filt_w  = (const float*)d_in[5];
    const float* filt_b  = (const float*)d_in[6];
    const float* out_w   = (const float*)d_in[7];
    const float* out_b   = (const float*)d_in[8];
    float* out = (float*)d_out;

    __half *px2, *py, *ppw, *pow_;
    cudaGetSymbolAddress((void**)&px2, g_x2);
    cudaGetSymbolAddress((void**)&py,  g_y);
    cudaGetSymbolAddress((void**)&ppw, g_pw);
    cudaGetSymbolAddress((void**)&pow_, g_ow);

    cudaFuncSetAttribute((const void*)gemm_h<1>, cudaFuncAttributeMaxDynamicSharedMemorySize, SMEM_BYTES);
    cudaFuncSetAttribute((const void*)gemm_h<0>, cudaFuncAttributeMaxDynamicSharedMemorySize, SMEM_BYTES);

    const int sthreads = 256;
    const int sblocks  = (BB * S4 * D4 + sthreads - 1) / sthreads;   // 4096

    // weight conversions
    {
        int n4 = (KK * NN) / 4;
        int blocks = (n4 + 255) / 256;
        convert_half_kernel<<<blocks, 256>>>(proj_w, ppw, n4);
        convert_half_kernel<<<blocks, 256>>>(out_w,  pow_, n4);
    }

    // 1. short conv residual -> x2 (fp16), 4 s-rows/thread
    shortconv_kernel<<<sblocks, sthreads>>>(x, short_w, short_b);

    // 2. fused: gelu(x2@proj_w + proj_b) folded with filt_w -> g_fs2
    dim3 ggrid(NN / BN, MM / BM);   // (16, 64)
    gemm_h<1><<<ggrid, 128, SMEM_BYTES>>>(px2, ppw, proj_b, nullptr, filt_w);

    // 3. per-row slot sums + tanh + block partials -> g_wpart (wreduce folded)
    fsum_kernel<<<MM/256, 256>>>(filt_b);

    // 4. y = gelu(conv(x2; w) * x) -> y fp16; w computed inline from g_wpart
    convgate_kernel<<<sblocks, sthreads>>>(x);

    // 5. out = y @ out_w + out_b — fp32 out
    gemm_h<0><<<ggrid, 128, SMEM_BYTES>>>(py, pow_, out_b, out, nullptr);
}

// round 17
// speedup vs baseline: 1.0265x; 1.0053x over previous
#include <cuda_runtime.h>
#include <cuda_fp16.h>
#include <math.h>
#include <stdint.h>

#define BB 4
#define SS 2048
#define DD 2048
#define DI 1024
#define MM (BB*SS)      // 8192
#define KK DD
#define NN DD
#define D4 (DD/4)
#define S4 (SS/4)       // 512

// GEMM tiling: CTA 128x128, 4 warps (2M x 2N), warp tile 64x64, BKK=64, 3 stages
#define BM 128
#define BN 128
#define BKK 64
#define ASZ (BM*BKK)    // 8192 halves
#define BSZ (BKK*BN)    // 8192 halves
#define NSTAGE 3
#define STG_H (ASZ + BSZ)
#define SMEM_BYTES (NSTAGE*STG_H*2)    // 98304

// ---------------- scratch ---------------------------------------------------
__device__ __half g_x2[(size_t)MM*KK];
__device__ __half g_y [(size_t)MM*KK];
__device__ __half g_pw[(size_t)KK*NN];
__device__ __half g_ow[(size_t)KK*NN];
__device__ float g_fs2[(size_t)MM*3*32];   // per-(row,k) partials x 32 column-groups
__device__ float g_wpart[32*3];            // per-fsum-block partial sums

__device__ __forceinline__ float geluf(float v) {
    return 0.5f * v * (1.0f + erff(v * 0.70710678118654752f));
}
__device__ __forceinline__ uint32_t smem_u32(const void* p) {
    return (uint32_t)__cvta_generic_to_shared(p);
}

#define CP16(s, g) asm volatile("cp.async.cg.shared.global [%0], [%1], 16;\n" :: "r"(s), "l"(g))
#define CP_COMMIT() asm volatile("cp.async.commit_group;\n")
#define LDSM4(R0,R1,R2,R3,addr) \
    asm volatile("ldmatrix.sync.aligned.m8n8.x4.shared.b16 {%0,%1,%2,%3},[%4];" \
                 : "=r"(R0),"=r"(R1),"=r"(R2),"=r"(R3) : "r"(addr))
#define LDSM4T(R0,R1,R2,R3,addr) \
    asm volatile("ldmatrix.sync.aligned.m8n8.x4.trans.shared.b16 {%0,%1,%2,%3},[%4];" \
                 : "=r"(R0),"=r"(R1),"=r"(R2),"=r"(R3) : "r"(addr))
#define MMAH16816(D0,D1,D2,D3,A0,A1,A2,A3,B0,B1) \
    asm volatile("mma.sync.aligned.m16n8k16.row.col.f32.f16.f16.f32 " \
                 "{%0,%1,%2,%3},{%4,%5,%6,%7},{%8,%9},{%0,%1,%2,%3};" \
                 : "+f"(D0),"+f"(D1),"+f"(D2),"+f"(D3) \
                 : "r"(A0),"r"(A1),"r"(A2),"r"(A3),"r"(B0),"r"(B1))

// ------- merged weight conversion: proj_w and out_w in one launch ----------
__global__ void convert_both_kernel(const float* __restrict__ pw,
                                    const float* __restrict__ ow)
{
    const int blk = blockIdx.x;            // 0..8191
    const float* src = (blk < 4096) ? pw : ow;
    __half* dst = (blk < 4096) ? g_pw : g_ow;
    int i = (blk & 4095) * 256 + threadIdx.x;
    size_t base = (size_t)i * 4;
    float4 v = *(const float4*)(src + base);
    *(__half2*)(dst + base)     = __floats2half2_rn(v.x, v.y);
    *(__half2*)(dst + base + 2) = __floats2half2_rn(v.z, v.w);
}

// ------- kernel 1: short conv + residual, 4 s-positions per thread ---------
__global__ void shortconv_kernel(const float* __restrict__ x,
                                 const float* __restrict__ sw,
                                 const float* __restrict__ sb)
{
    int idx = blockIdx.x * blockDim.x + threadIdx.x;
    if (idx >= BB * S4 * D4) return;
    int d4 = idx % D4;
    int g  = idx / D4;
    int s0 = (g & (S4 - 1)) * 4;
    int b  = g >> 9;           // S4 = 512
    int d  = d4 * 4;
    size_t rowbase = ((size_t)(b*SS + s0))*DD + d;

    float4 r[6];               // rows s0-2 .. s0+3
    #pragma unroll
    for (int i = 0; i < 6; i++) {
        int s = s0 + i - 2;
        r[i] = (s >= 0) ? *(const float4*)(x + rowbase + (ptrdiff_t)(i-2)*DD)
                        : make_float4(0.f, 0.f, 0.f, 0.f);
    }
    float w0[4], w1[4], w2[4], bb[4];
    #pragma unroll
    for (int q = 0; q < 4; q++) {
        w0[q] = sw[(d+q)*3+0]; w1[q] = sw[(d+q)*3+1]; w2[q] = sw[(d+q)*3+2];
        bb[q] = sb[d+q];
    }
    #pragma unroll
    for (int i = 0; i < 4; i++) {
        const float cv[4] = {r[i+2].x, r[i+2].y, r[i+2].z, r[i+2].w};
        const float pv[4] = {r[i+1].x, r[i+1].y, r[i+1].z, r[i+1].w};
        const float qv[4] = {r[i].x,   r[i].y,   r[i].z,   r[i].w};
        float o[4];
        #pragma unroll
        for (int q = 0; q < 4; q++)
            o[q] = cv[q] + bb[q] + qv[q]*w0[q] + pv[q]*w1[q] + cv[q]*w2[q];
        size_t ob = rowbase + (size_t)i*DD;
        *(__half2*)(g_x2 + ob)     = __floats2half2_rn(o[0], o[1]);
        *(__half2*)(g_x2 + ob + 2) = __floats2half2_rn(o[2], o[3]);
    }
}

// ---------------- fp16 tensor-core GEMM, 128x128 tile, 2 CTAs/SM -----------
template<int REDUCE>
__global__ void __launch_bounds__(128, 2)
gemm_h(const __half* __restrict__ A, const __half* __restrict__ B,
       const float* __restrict__ bias, float* __restrict__ C,
       const float* __restrict__ fw)
{
    extern __shared__ __half sm[];

    const int tid  = threadIdx.x;
    const int bm   = blockIdx.y, bn = blockIdx.x;
    const int warp = tid >> 5, lane = tid & 31;
    const int mwarp = (warp & 1) * 64;
    const int nwarp = (warp >> 1) * 64;

    const uint32_t base0 = smem_u32(sm);

    auto issue = [&](int stg, int t) {
        uint32_t aS = base0 + (uint32_t)stg*STG_H*2;
        uint32_t bS = aS + ASZ*2;
        const __half* gAt = A + (size_t)(bm*BM)*KK + (size_t)t*BKK;
        const __half* gBt = B + (size_t)((size_t)t*BKK)*NN + bn*BN;
        #pragma unroll
        for (int j = 0; j < 8; j++) {
            int idx = tid + 128*j;
            int row = idx >> 3, ch = idx & 7;
            uint32_t so = (uint32_t)row*128u + (uint32_t)(((ch ^ (row & 7)) << 4));
            CP16(aS + so, gAt + (size_t)row*KK + ch*8);
        }
        #pragma unroll
        for (int j = 0; j < 8; j++) {
            int idx = tid + 128*j;
            int row = idx >> 4, ch = idx & 15;
            uint32_t so = (uint32_t)row*256u + (uint32_t)(((ch ^ (row & 7)) << 4));
            CP16(bS + so, gBt + (size_t)row*NN + ch*8);
        }
        CP_COMMIT();
    };

    float acc[4][8][4];
    #pragma unroll
    for (int i = 0; i < 4; i++)
        #pragma unroll
        for (int j = 0; j < 8; j++)
            #pragma unroll
            for (int q = 0; q < 4; q++) acc[i][j][q] = 0.f;

    const int lr  = lane & 15;
    const int hc  = lane >> 4;
    const int swz = lr & 7;
    int rowA[4];
    #pragma unroll
    for (int mt = 0; mt < 4; mt++) rowA[mt] = mwarp + mt*16 + lr;
    const int ncbase = (warp >> 1) * 8;

    uint32_t af[2][4][4];
    uint32_t bf[2][4];

    const int NT = KK / BKK;               // 32
    issue(0, 0);
    issue(1, 1);

    for (int t = 0; t < NT; ++t) {
        const int stg = t % NSTAGE;
        asm volatile("cp.async.wait_group %0;\n" :: "n"(NSTAGE - 2));
        __syncthreads();
        if (t + 2 < NT) issue((t + 2) % NSTAGE, t + 2);

        const uint32_t aS = base0 + (uint32_t)stg*STG_H*2;
        const uint32_t bS = aS + ASZ*2;

        // preload ks=0 fragments
        {
            int chunk = hc ^ swz;
            #pragma unroll
            for (int mt = 0; mt < 4; mt++)
                LDSM4(af[0][mt][0], af[0][mt][1], af[0][mt][2], af[0][mt][3],
                      aS + (uint32_t)rowA[mt]*128 + chunk*16);
            int bchunk = (ncbase + hc) ^ swz;
            LDSM4T(bf[0][0], bf[0][1], bf[0][2], bf[0][3],
                   bS + (uint32_t)lr*256 + bchunk*16);
        }

        #pragma unroll
        for (int ks = 0; ks < 4; ks++) {
            const int krow = ks*16 + lr;
            const int cab = ks & 1;
            #pragma unroll
            for (int p = 0; p < 4; p++) {
                const int cb = p & 1, nb = cb ^ 1;
                if (p < 3) {
                    int chunk = (ncbase + 2*(p+1) + hc) ^ swz;
                    LDSM4T(bf[nb][0], bf[nb][1], bf[nb][2], bf[nb][3],
                           bS + (uint32_t)krow*256 + chunk*16);
                } else if (ks < 3) {
                    int achunk = (2*(ks+1) + hc) ^ swz;
                    #pragma unroll
                    for (int mt = 0; mt < 4; mt++)
                        LDSM4(af[cab^1][mt][0], af[cab^1][mt][1], af[cab^1][mt][2], af[cab^1][mt][3],
                              aS + (uint32_t)rowA[mt]*128 + achunk*16);
                    int bchunk = (ncbase + hc) ^ swz;
                    LDSM4T(bf[nb][0], bf[nb][1], bf[nb][2], bf[nb][3],
                           bS + (uint32_t)(krow + 16)*256 + bchunk*16);
                }
                #pragma unroll
                for (int mt = 0; mt < 4; mt++) {
                    MMAH16816(acc[mt][2*p+0][0],acc[mt][2*p+0][1],acc[mt][2*p+0][2],acc[mt][2*p+0][3],
                              af[cab][mt][0],af[cab][mt][1],af[cab][mt][2],af[cab][mt][3],
                              bf[cb][0],bf[cb][1]);
                    MMAH16816(acc[mt][2*p+1][0],acc[mt][2*p+1][1],acc[mt][2*p+1][2],acc[mt][2*p+1][3],
                              af[cab][mt][0],af[cab][mt][1],af[cab][mt][2],af[cab][mt][3],
                              bf[cb][2],bf[cb][3]);
                }
            }
        }
    }

    // ---- epilogue ----
    const int g  = lane >> 2;
    const int tg = lane & 3;

    if (REDUCE) {
        float part[4][2][3];
        #pragma unroll
        for (int mt = 0; mt < 4; mt++)
            #pragma unroll
            for (int r = 0; r < 2; r++)
                #pragma unroll
                for (int k = 0; k < 3; k++) part[mt][r][k] = 0.f;

        #pragma unroll
        for (int nn = 0; nn < 8; nn++) {
            const int col = bn*BN + nwarp + nn*8 + tg*2;
            const float b0 = bias[col], b1 = bias[col+1];
            const int i0 = col & (DI-1);
            float fw0[3], fw1[3];
            #pragma unroll
            for (int k = 0; k < 3; k++) { fw0[k] = fw[i0*3+k]; fw1[k] = fw[(i0+1)*3+k]; }
            #pragma unroll
            for (int mt = 0; mt < 4; mt++) {
                float v0 = geluf(acc[mt][nn][0] + b0);
                float v1 = geluf(acc[mt][nn][1] + b1);
                float v2 = geluf(acc[mt][nn][2] + b0);
                float v3 = geluf(acc[mt][nn][3] + b1);
                #pragma unroll
                for (int k = 0; k < 3; k++) {
                    part[mt][0][k] += v0*fw0[k] + v1*fw1[k];
                    part[mt][1][k] += v2*fw0[k] + v3*fw1[k];
                }
            }
        }
        #pragma unroll
        for (int mt = 0; mt < 4; mt++)
            #pragma unroll
            for (int r = 0; r < 2; r++)
                #pragma unroll
                for (int k = 0; k < 3; k++) {
                    float v = part[mt][r][k];
                    v += __shfl_xor_sync(0xffffffffu, v, 1);
                    v += __shfl_xor_sync(0xffffffffu, v, 2);
                    part[mt][r][k] = v;
                }
        if (tg == 0) {
            const int slot = bn*2 + (nwarp >> 6);   // 0..31
            #pragma unroll
            for (int mt = 0; mt < 4; mt++)
                #pragma unroll
                for (int r = 0; r < 2; r++) {
                    const int bs = bm*BM + mwarp + mt*16 + r*8 + g;
                    #pragma unroll
                    for (int k = 0; k < 3; k++)
                        g_fs2[((size_t)bs*3 + k)*32 + slot] = part[mt][r][k];
                }
        }
    } else {
        #pragma unroll
        for (int nn = 0; nn < 8; nn++) {
            const int col = bn*BN + nwarp + nn*8 + tg*2;
            const float b0 = bias[col], b1 = bias[col+1];
            #pragma unroll
            for (int mt = 0; mt < 4; mt++) {
                const int row0 = bm*BM + mwarp + mt*16 + g;
                *(float2*)(C + (size_t)row0*NN + col)     = make_float2(acc[mt][nn][0] + b0, acc[mt][nn][1] + b1);
                *(float2*)(C + (size_t)(row0+8)*NN + col) = make_float2(acc[mt][nn][2] + b0, acc[mt][nn][3] + b1);
            }
        }
    }
}

// ---- stage 1: per-row slot sums + tanh, then block partial -> g_wpart ------
__global__ void fsum_kernel(const float* __restrict__ fb)
{
    int bs = blockIdx.x * blockDim.x + threadIdx.x;
    const float4* p = (const float4*)(g_fs2 + (size_t)bs * 96);
    float out[3];
    #pragma unroll
    for (int k = 0; k < 3; k++) {
        float t0 = 0.f, t1 = 0.f;
        #pragma unroll
        for (int j = 0; j < 4; j++) {
            float4 v = p[k*8 + j];
            t0 += (v.x + v.y) + (v.z + v.w);
        }
        #pragma unroll
        for (int j = 4; j < 8; j++) {
            float4 v = p[k*8 + j];
            t1 += (v.x + v.y) + (v.z + v.w);
        }
        out[k] = tanhf(t0 + fb[k]) + tanhf(t1 + fb[k]);
    }
    #pragma unroll
    for (int off = 16; off; off >>= 1)
        #pragma unroll
        for (int k = 0; k < 3; k++)
            out[k] += __shfl_xor_sync(0xffffffffu, out[k], off);

    __shared__ float red[8][3];
    int warp = threadIdx.x >> 5, lane = threadIdx.x & 31;
    if (lane == 0) { red[warp][0] = out[0]; red[warp][1] = out[1]; red[warp][2] = out[2]; }
    __syncthreads();
    if (threadIdx.x == 0) {
        float s0 = 0.f, s1 = 0.f, s2 = 0.f;
        #pragma unroll
        for (int w = 0; w < 8; w++) { s0 += red[w][0]; s1 += red[w][1]; s2 += red[w][2]; }
        g_wpart[blockIdx.x*3+0] = s0;
        g_wpart[blockIdx.x*3+1] = s1;
        g_wpart[blockIdx.x*3+2] = s2;
    }
}

// -------- kernel 5: gated conv * v, gelu -> y; computes w inline ------------
__global__ void convgate_kernel(const float* __restrict__ x)
{
    int idx = blockIdx.x * blockDim.x + threadIdx.x;
    if (idx >= BB * S4 * D4) return;
    int d4 = idx % D4;
    int g  = idx / D4;
    int s0 = (g & (S4 - 1)) * 4;
    int b  = g >> 9;
    size_t rowbase = ((size_t)(b*SS + s0))*DD + d4*4;

    float w0 = 0.f, w1 = 0.f, w2 = 0.f;
    #pragma unroll
    for (int j = 0; j < 8; j++) {
        const float* p = g_wpart + (b*8 + j)*3;
        w0 += p[0]; w1 += p[1]; w2 += p[2];
    }
    const float inv = 1.0f / (float)SS;
    w0 *= inv; w1 *= inv; w2 *= inv;

    float c[6][4];
    #pragma unroll
    for (int i = 0; i < 6; i++) {
        int s = s0 + i - 2;
        if (s >= 0) {
            size_t p = rowbase + (ptrdiff_t)(i-2)*DD;
            __half2 p0 = *(const __half2*)(g_x2 + p);
            __half2 p1 = *(const __half2*)(g_x2 + p + 2);
            c[i][0] = __low2float(p0); c[i][1] = __high2float(p0);
            c[i][2] = __low2float(p1); c[i][3] = __high2float(p1);
        } else {
            c[i][0] = c[i][1] = c[i][2] = c[i][3] = 0.f;
        }
    }
    #pragma unroll
    for (int i = 0; i < 4; i++) {
        size_t p = rowbase + (size_t)i*DD;
        float4 v = *(const float4*)(x + p);
        const float vv[4] = {v.x, v.y, v.z, v.w};
        float o[4];
        #pragma unroll
        for (int q = 0; q < 4; q++)
            o[q] = geluf((c[i][q]*w0 + c[i+1][q]*w1 + c[i+2][q]*w2) * vv[q]);
        *(__half2*)(g_y + p)     = __floats2half2_rn(o[0], o[1]);
        *(__half2*)(g_y + p + 2) = __floats2half2_rn(o[2], o[3]);
    }
}

// ---------------- launcher ---------------------------------------------------
extern "C" void kernel_launch(void* const* d_in, const int* in_sizes, int n_in,
                              void* d_out, int out_size)
{
    const float* x       = (const float*)d_in[0];
    const float* short_w = (const float*)d_in[1];
    const float* short_b = (const float*)d_in[2];
    const float* proj_w  = (const float*)d_in[3];
    const float* proj_b  = (const float*)d_in[4];
    const float* filt_w  = (const float*)d_in[5];
    const float* filt_b  = (const float*)d_in[6];
    const float* out_w   = (const float*)d_in[7];
    const float* out_b   = (const float*)d_in[8];
    float* out = (float*)d_out;

    __half *px2, *py, *ppw, *pow_;
    cudaGetSymbolAddress((void**)&px2, g_x2);
    cudaGetSymbolAddress((void**)&py,  g_y);
    cudaGetSymbolAddress((void**)&ppw, g_pw);
    cudaGetSymbolAddress((void**)&pow_, g_ow);

    cudaFuncSetAttribute((const void*)gemm_h<1>, cudaFuncAttributeMaxDynamicSharedMemorySize, SMEM_BYTES);
    cudaFuncSetAttribute((const void*)gemm_h<0>, cudaFuncAttributeMaxDynamicSharedMemorySize, SMEM_BYTES);

    const int sthreads = 256;
    const int sblocks  = (BB * S4 * D4 + sthreads - 1) / sthreads;   // 4096

    // 0. both weight conversions in a single launch
    convert_both_kernel<<<8192, 256>>>(proj_w, out_w);

    // 1. short conv residual -> x2 (fp16), 4 s-rows/thread
    shortconv_kernel<<<sblocks, sthreads>>>(x, short_w, short_b);

    // 2. fused: gelu(x2@proj_w + proj_b) folded with filt_w -> g_fs2
    dim3 ggrid(NN / BN, MM / BM);   // (16, 64)
    gemm_h<1><<<ggrid, 128, SMEM_BYTES>>>(px2, ppw, proj_b, nullptr, filt_w);

    // 3. per-row slot sums + tanh + block partials -> g_wpart
    fsum_kernel<<<MM/256, 256>>>(filt_b);

    // 4. y = gelu(conv(x2; w) * x) -> y fp16; w computed inline from g_wpart
    convgate_kernel<<<sblocks, sthreads>>>(x);

    // 5. out = y @ out_w + out_b — fp32 out
    gemm_h<0><<<ggrid, 128, SMEM_BYTES>>>(py, pow_, out_b, out, nullptr);
}